// round 14
// baseline (speedup 1.0000x reference)
#include <cuda_runtime.h>
#include <cuda_fp16.h>
#include <math.h>

#define NPAT 100000
#define NLAB 10000
#define NDIS 500
#define NE1  2000000
#define NE2  500000
#define H    128
#define HH   (128*128)
#define FC1C 64
#define NOUT 10
#define EPSBN 1e-5f

#define NTOTI (NLAB + NDIS + NPAT + NPAT)
#define STILE 1024
#define SNB   ((NTOTI + STILE - 1) / STILE)

// ---------------- scratch layout ----------------
constexpr long SZ_HP = (long)NPAT * H;
constexpr long SZ_HL = (long)NLAB * H;
constexpr long SZ_HD = (long)NDIS * H;

constexpr long O_HP0 = 0;
constexpr long O_HP1 = O_HP0 + SZ_HP;
constexpr long O_HL0 = O_HP1 + SZ_HP;
constexpr long O_HL1 = O_HL0 + SZ_HL;
constexpr long O_HD0 = O_HL1 + SZ_HL;
constexpr long O_HD1 = O_HD0 + SZ_HD;
constexpr long O_TL  = O_HD1 + SZ_HD;
constexpr long O_TD  = O_TL + SZ_HL;
constexpr long O_WT  = O_TD + SZ_HD;
constexpr long O_T1  = O_WT + HH;
constexpr long O_LA  = O_T1 + (long)NPAT * FC1C;
constexpr long O_HP16 = O_LA + SZ_HL;
constexpr long O_TL16 = O_HP16 + SZ_HP / 2;
constexpr long O_TD16 = O_TL16 + SZ_HL / 2;
// --- zero-once region: da0 | da1 | sm[6H] | sq[6H] | counts[NTOTI] ---
constexpr long O_DA0 = O_TD16 + SZ_HD / 2;
constexpr long O_DA1 = O_DA0 + SZ_HD;
constexpr long O_SM  = O_DA1 + SZ_HD;          // 6 slots of H
constexpr long O_SQ  = O_SM + 6 * H;
constexpr long O_CL  = O_SQ + 6 * H;           // combined counts [NTOTI]
constexpr long O_OFF = O_CL + NTOTI;           // CSR offsets [NTOTI+1]
constexpr long O_CUR = O_OFF + NTOTI + 4;
constexpr long O_PART= O_CUR + NTOTI;
constexpr long O_ADJ = O_PART + 512;
constexpr long O_END = O_ADJ + 2L * (NE1 + NE2);

constexpr long Z_N4  = (O_OFF - O_DA0) / 4;    // startup zero span
constexpr long TOT4  = (O_END + 3) / 4;

__device__ float4 g_buf[TOT4];

// ---------------- utility kernels ----------------

__global__ void k_zero4(float4* p, long n4) {
    long i  = (long)blockIdx.x * blockDim.x + threadIdx.x;
    long st = (long)gridDim.x * blockDim.x;
    float4 z = make_float4(0.f, 0.f, 0.f, 0.f);
    for (; i < n4; i += st) p[i] = z;
}

__global__ void k_count(const int* __restrict__ src, const int* __restrict__ dst, int n,
                        int* cs, int* cd) {
    int i  = blockIdx.x * blockDim.x + threadIdx.x;
    int st = gridDim.x * blockDim.x;
    for (; i < n; i += st) {
        atomicAdd(cs + src[i], 1);
        atomicAdd(cd + dst[i], 1);
    }
}

__global__ void k_psum(const int* __restrict__ cnt, int* __restrict__ part) {
    __shared__ int wsum[8];
    int t = threadIdx.x;
    long base = (long)blockIdx.x * STILE + t * 4;
    int s = 0;
#pragma unroll
    for (int u = 0; u < 4; u++) {
        long i = base + u;
        if (i < NTOTI) s += cnt[i];
    }
#pragma unroll
    for (int o = 16; o > 0; o >>= 1) s += __shfl_xor_sync(0xffffffffu, s, o);
    if ((t & 31) == 0) wsum[t >> 5] = s;
    __syncthreads();
    if (t == 0) {
        int tot = 0;
#pragma unroll
        for (int i = 0; i < 8; i++) tot += wsum[i];
        part[blockIdx.x] = tot;
    }
}

__global__ void k_scanpart(int* __restrict__ part, int* __restrict__ off_end) {
    __shared__ int sh[256];
    int t = threadIdx.x;
    int v = (t < SNB) ? part[t] : 0;
    sh[t] = v;
    __syncthreads();
#pragma unroll
    for (int d = 1; d < 256; d <<= 1) {
        int x = (t >= d) ? sh[t - d] : 0;
        __syncthreads();
        sh[t] += x;
        __syncthreads();
    }
    if (t < SNB) part[t] = sh[t] - v;
    if (t == 255) *off_end = sh[255];
}

__global__ void k_scanfinal(const int* __restrict__ cnt, const int* __restrict__ part,
                            int* __restrict__ off, int* __restrict__ cur) {
    __shared__ int wpre[8];
    int t = threadIdx.x, lane = t & 31, w = t >> 5;
    long base = (long)blockIdx.x * STILE + t * 4;
    int v[4];
    int s = 0;
#pragma unroll
    for (int u = 0; u < 4; u++) {
        v[u] = (base + u < NTOTI) ? cnt[base + u] : 0;
        s += v[u];
    }
    int incl = s;
#pragma unroll
    for (int o = 1; o < 32; o <<= 1) {
        int x = __shfl_up_sync(0xffffffffu, incl, o);
        if (lane >= o) incl += x;
    }
    int excl = incl - s;
    if (lane == 31) wpre[w] = incl;
    __syncthreads();
    if (t == 0) {
        int run = 0;
#pragma unroll
        for (int i = 0; i < 8; i++) { int x = wpre[i]; wpre[i] = run; run += x; }
    }
    __syncthreads();
    int pre = part[blockIdx.x] + wpre[w] + excl;
#pragma unroll
    for (int u = 0; u < 4; u++) {
        if (base + u < NTOTI) { off[base + u] = pre; cur[base + u] = pre; }
        pre += v[u];
    }
}

__global__ void k_fill(const int* __restrict__ src, const int* __restrict__ dst, int n,
                       int* curd, int* curs, int* __restrict__ adj) {
    int i  = blockIdx.x * blockDim.x + threadIdx.x;
    int st = gridDim.x * blockDim.x;
    for (; i < n; i += st) {
        int s = src[i], d = dst[i];
        adj[atomicAdd(curd + d, 1)] = s;
        adj[atomicAdd(curs + s, 1)] = d;
    }
}

// ---------------- embeddings ----------------

__global__ void k_embed_pat(const float* __restrict__ x, const float* __restrict__ Wp,
                            const float* __restrict__ bp, float* __restrict__ out,
                            __half* __restrict__ out16) {
    __shared__ float Wsh[16 * H];
    __shared__ float xsh[8][16];
    int tid = threadIdx.x;
    for (int i = tid; i < 16 * H; i += 128) Wsh[i] = Wp[i];
    __syncthreads();
    float wreg[16];
#pragma unroll
    for (int k = 0; k < 16; k++) wreg[k] = Wsh[k * H + tid];
    float bb = bp[tid];
    for (long base = (long)blockIdx.x * 8; base < NPAT; base += (long)gridDim.x * 8) {
        int nr = (int)((NPAT - base) < 8 ? (NPAT - base) : 8);
        if (tid < nr * 16) xsh[tid >> 4][tid & 15] = x[base * 16 + tid];
        __syncthreads();
        for (int r = 0; r < nr; r++) {
            float acc = bb;
#pragma unroll
            for (int k = 0; k < 16; k++) acc = fmaf(xsh[r][k], wreg[k], acc);
            long o = (base + r) * H + tid;
            out[o]   = acc;
            out16[o] = __float2half_rn(acc);
        }
        __syncthreads();
    }
}

__global__ void k_embed_lab(const float* __restrict__ x, const float* __restrict__ W,
                            const float* __restrict__ b, float* __restrict__ out) {
    long idx = (long)blockIdx.x * blockDim.x + threadIdx.x;
    if (idx >= (long)NLAB * H) return;
    int i = (int)(idx >> 7), h = (int)(idx & 127);
    out[idx] = x[i] * W[h] + b[h];
}

__global__ void k_embed_dis(const float* __restrict__ x, const float* __restrict__ W,
                            const float* __restrict__ b, float* __restrict__ out) {
    long idx = (long)blockIdx.x * blockDim.x + threadIdx.x;
    if (idx >= (long)NDIS * H) return;
    int i = (int)(idx >> 7), h = (int)(idx & 127);
    out[idx] = x[2 * i] * W[h] + x[2 * i + 1] * W[H + h] + b[h];
}

// ---------------- gather aggregation (fp16 sources, fp32 accumulate) --------

__device__ __forceinline__ void red4(float* p, float4 v) {
    asm volatile("red.global.add.v4.f32 [%0], {%1,%2,%3,%4};"
                 :: "l"(p), "f"(v.x), "f"(v.y), "f"(v.z), "f"(v.w) : "memory");
}

__device__ __forceinline__ void acc8(float4& acc, uint2 u) {
    __half2 h0 = *(__half2*)&u.x;
    __half2 h1 = *(__half2*)&u.y;
    float2 f0 = __half22float2(h0);
    float2 f1 = __half22float2(h1);
    acc.x += f0.x; acc.y += f0.y; acc.z += f1.x; acc.w += f1.y;
}

__device__ __forceinline__ float4 gmean16(const int* __restrict__ off,
                                          const int* __restrict__ adj,
                                          const __half* __restrict__ src,
                                          int row, int lane) {
    int s = off[row], e = off[row + 1];
    float4 acc = make_float4(0.f, 0.f, 0.f, 0.f);
    int j = s;
    for (; j + 4 <= e; j += 4) {
        int i0 = __ldg(adj + j),     i1 = __ldg(adj + j + 1);
        int i2 = __ldg(adj + j + 2), i3 = __ldg(adj + j + 3);
        uint2 u0 = __ldg((const uint2*)(src + (size_t)i0 * H) + lane);
        uint2 u1 = __ldg((const uint2*)(src + (size_t)i1 * H) + lane);
        uint2 u2 = __ldg((const uint2*)(src + (size_t)i2 * H) + lane);
        uint2 u3 = __ldg((const uint2*)(src + (size_t)i3 * H) + lane);
        acc8(acc, u0); acc8(acc, u1); acc8(acc, u2); acc8(acc, u3);
    }
    for (; j < e; j++) {
        int i0 = __ldg(adj + j);
        uint2 u = __ldg((const uint2*)(src + (size_t)i0 * H) + lane);
        acc8(acc, u);
    }
    float r = 1.f / fmaxf((float)(e - s), 1.f);
    acc.x *= r; acc.y *= r; acc.z *= r; acc.w *= r;
    return acc;
}

__global__ void k_gather_mean(const int* __restrict__ off, const int* __restrict__ adj,
                              const __half* __restrict__ src, float* __restrict__ out,
                              int Nd) {
    int w    = (blockIdx.x * blockDim.x + threadIdx.x) >> 5;
    int lane = threadIdx.x & 31;
    if (w >= Nd) return;
    float4 m = gmean16(off, adj, src, w, lane);
    ((float4*)(out + (size_t)w * H))[lane] = m;
}

__global__ void k_gather_mean_w8(const int* __restrict__ off, const int* __restrict__ adj,
                                 const __half* __restrict__ src, float* __restrict__ out,
                                 int Nd) {
    int gw   = (blockIdx.x * blockDim.x + threadIdx.x) >> 5;
    int lane = threadIdx.x & 31;
    int row  = gw >> 3, sub = gw & 7;
    if (row >= Nd) return;
    int s = off[row], e = off[row + 1];
    float4 acc = make_float4(0.f, 0.f, 0.f, 0.f);
    int j = s + sub * 4;
    for (; j + 4 <= e; j += 32) {
        int i0 = __ldg(adj + j),     i1 = __ldg(adj + j + 1);
        int i2 = __ldg(adj + j + 2), i3 = __ldg(adj + j + 3);
        uint2 u0 = __ldg((const uint2*)(src + (size_t)i0 * H) + lane);
        uint2 u1 = __ldg((const uint2*)(src + (size_t)i1 * H) + lane);
        uint2 u2 = __ldg((const uint2*)(src + (size_t)i2 * H) + lane);
        uint2 u3 = __ldg((const uint2*)(src + (size_t)i3 * H) + lane);
        acc8(acc, u0); acc8(acc, u1); acc8(acc, u2); acc8(acc, u3);
    }
    if (j < e) {
        for (int t = j; t < e; t++) {
            int i0 = __ldg(adj + t);
            uint2 u = __ldg((const uint2*)(src + (size_t)i0 * H) + lane);
            acc8(acc, u);
        }
    }
    float r = 1.f / fmaxf((float)(e - s), 1.f);
    acc.x *= r; acc.y *= r; acc.z *= r; acc.w *= r;
    red4((float*)((float4*)(out + (size_t)row * H) + lane), acc);
}

__global__ void k_gather_pat(const int* __restrict__ off1, const int* __restrict__ adj1,
                             const __half* __restrict__ srcL,
                             const int* __restrict__ off2, const int* __restrict__ adj2,
                             const __half* __restrict__ srcD,
                             const float* __restrict__ b2, const float* __restrict__ b3,
                             float* __restrict__ out) {
    int w    = (blockIdx.x * blockDim.x + threadIdx.x) >> 5;
    int lane = threadIdx.x & 31;
    if (w >= NPAT) return;
    float4 a1 = gmean16(off1, adj1, srcL, w, lane);
    float4 a2 = gmean16(off2, adj2, srcD, w, lane);
    float4 bb2 = ((const float4*)b2)[lane];
    float4 bb3 = ((const float4*)b3)[lane];
    float4* o = (float4*)(out + (size_t)w * H) + lane;
    float4 v = *o;
    v.x += a1.x + a2.x + bb2.x + bb3.x;
    v.y += a1.y + a2.y + bb2.y + bb3.y;
    v.z += a1.z + a2.z + bb2.z + bb3.z;
    v.w += a1.w + a2.w + bb2.w + bb3.w;
    *o = v;
}

// ---------------- GEMM [N,128] @ [128,NC], 8 rows per tile ----------------
#define GF_ACC 1
#define GF_RELU 2
__global__ void __launch_bounds__(128) k_gemm(const float* __restrict__ A,
                                              const float* __restrict__ W,
                                              const float* __restrict__ bias,
                                              float* __restrict__ out,
                                              __half* __restrict__ out16,
                                              int N, int flags) {
    extern __shared__ float Wsh[];
    __shared__ float4 ashA[H];
    __shared__ float4 ashB[H];
    int NC  = blockDim.x;
    int tid = threadIdx.x;
    for (int i = tid; i < H * NC; i += NC) Wsh[i] = W[i];
    __syncthreads();
    float bb = bias ? bias[tid] : 0.f;
    for (long base = (long)blockIdx.x * 8; base < N; base += (long)gridDim.x * 8) {
        int nr = (int)(((long)N - base) < 8 ? ((long)N - base) : 8);
        for (int k = tid; k < H; k += NC) {
            const float* Ak = A + base * H + k;
            float4 va, vb;
            va.x = Ak[0];
            va.y = nr > 1 ? Ak[1 * H] : 0.f;
            va.z = nr > 2 ? Ak[2 * H] : 0.f;
            va.w = nr > 3 ? Ak[3 * H] : 0.f;
            vb.x = nr > 4 ? Ak[4 * H] : 0.f;
            vb.y = nr > 5 ? Ak[5 * H] : 0.f;
            vb.z = nr > 6 ? Ak[6 * H] : 0.f;
            vb.w = nr > 7 ? Ak[7 * H] : 0.f;
            ashA[k] = va;
            ashB[k] = vb;
        }
        __syncthreads();
        float a0 = bb, a1 = bb, a2 = bb, a3 = bb;
        float a4 = bb, a5 = bb, a6 = bb, a7 = bb;
#pragma unroll 16
        for (int k = 0; k < H; k++) {
            float4 av = ashA[k];
            float4 bv = ashB[k];
            float wv  = Wsh[k * NC + tid];
            a0 = fmaf(av.x, wv, a0);
            a1 = fmaf(av.y, wv, a1);
            a2 = fmaf(av.z, wv, a2);
            a3 = fmaf(av.w, wv, a3);
            a4 = fmaf(bv.x, wv, a4);
            a5 = fmaf(bv.y, wv, a5);
            a6 = fmaf(bv.z, wv, a6);
            a7 = fmaf(bv.w, wv, a7);
        }
        float rr[8] = {a0, a1, a2, a3, a4, a5, a6, a7};
        for (int r = 0; r < nr; r++) {
            long o  = (base + r) * NC + tid;
            float v = rr[r];
            if (flags & GF_ACC)  v += out[o];
            if (flags & GF_RELU) v = fmaxf(v, 0.f);
            out[o] = v;
            if (out16) out16[o] = __float2half_rn(v);
        }
        __syncthreads();
    }
}

__global__ void k_addw(const float* __restrict__ A, const float* __restrict__ Bm,
                       float* __restrict__ out) {
    int idx = blockIdx.x * blockDim.x + threadIdx.x;
    if (idx < HH) out[idx] = A[idx] + Bm[idx];
}

// ---------------- BatchNorm ----------------
__global__ void k_stats(const float* __restrict__ X, int N,
                        float* __restrict__ sum, float* __restrict__ sumsq) {
    int tid = threadIdx.x;
    float s = 0.f, ss = 0.f;
    for (long r = blockIdx.x; r < N; r += gridDim.x) {
        float v = X[r * H + tid];
        s += v;
        ss = fmaf(v, v, ss);
    }
    atomicAdd(sum + tid, s);
    atomicAdd(sumsq + tid, ss);
}

__global__ void k_bn(float* __restrict__ X, __half* __restrict__ X16, long n, float invN,
                     const float* __restrict__ sum, const float* __restrict__ sumsq,
                     const float* __restrict__ g, const float* __restrict__ b) {
    long idx = (long)blockIdx.x * blockDim.x + threadIdx.x;
    long st  = (long)gridDim.x * blockDim.x;
    for (; idx < n; idx += st) {
        int h   = (int)(idx & 127);
        float m = sum[h] * invN;
        float var = sumsq[h] * invN - m * m;
        float v = (X[idx] - m) * rsqrtf(var + EPSBN) * g[h] + b[h];
        v = fmaxf(v, 0.f);
        X[idx] = v;
        if (X16) X16[idx] = __float2half_rn(v);
    }
}

// ---------------- head ----------------
__global__ void k_head(const float* __restrict__ T, const float* __restrict__ W2,
                       const float* __restrict__ b2, float* __restrict__ out) {
    __shared__ float tsh[4][64];
    int w    = threadIdx.x >> 5;
    int lane = threadIdx.x & 31;
    long row = (long)blockIdx.x * 4 + w;
    if (row >= NPAT) return;
    tsh[w][lane]      = T[row * 64 + lane];
    tsh[w][lane + 32] = T[row * 64 + 32 + lane];
    __syncwarp();
    float z;
    if (lane < NOUT) {
        z = b2[lane];
#pragma unroll 8
        for (int j = 0; j < 64; j++) z = fmaf(tsh[w][j], __ldg(W2 + j * NOUT + lane), z);
    } else {
        z = -INFINITY;
    }
    float m = z;
#pragma unroll
    for (int off = 16; off > 0; off >>= 1) m = fmaxf(m, __shfl_xor_sync(0xffffffffu, m, off));
    float e = (lane < NOUT) ? __expf(z - m) : 0.f;
    float ssum = e;
#pragma unroll
    for (int off = 16; off > 0; off >>= 1) ssum += __shfl_xor_sync(0xffffffffu, ssum, off);
    float lse = m + __logf(ssum);
    if (lane < NOUT) out[row * NOUT + lane] = z - lse;
}

// ---------------- host ----------------
extern "C" void kernel_launch(void* const* d_in, const int* in_sizes, int n_in,
                              void* d_out, int out_size) {
    const float* x_pat = (const float*)d_in[0];
    const float* x_lab = (const float*)d_in[1];
    const float* x_dis = (const float*)d_in[2];
    const float* Wp    = (const float*)d_in[3];
    const float* bp    = (const float*)d_in[4];
    const float* Wlab  = (const float*)d_in[5];
    const float* blab  = (const float*)d_in[6];
    const float* Wdis  = (const float*)d_in[7];
    const float* bdis  = (const float*)d_in[8];
    const float* Wl[2] = {(const float*)d_in[9],  (const float*)d_in[12]};
    const float* bl[2] = {(const float*)d_in[10], (const float*)d_in[13]};
    const float* Wr[2] = {(const float*)d_in[11], (const float*)d_in[14]};
    const float* bng[2] = {(const float*)d_in[15], (const float*)d_in[17]};
    const float* bnb[2] = {(const float*)d_in[16], (const float*)d_in[18]};
    const float* fc1W  = (const float*)d_in[19];
    const float* fc1b  = (const float*)d_in[20];
    const float* fc2W  = (const float*)d_in[21];
    const float* fc2b  = (const float*)d_in[22];
    const int* s1 = (const int*)d_in[23];
    const int* d1 = (const int*)d_in[24];
    const int* s2 = (const int*)d_in[25];
    const int* d2 = (const int*)d_in[26];

    float* B = nullptr;
    cudaGetSymbolAddress((void**)&B, g_buf);

    float* hp[2] = {B + O_HP0, B + O_HP1};
    float* hl[2] = {B + O_HL0, B + O_HL1};
    float* hd[2] = {B + O_HD0, B + O_HD1};
    float* tl = B + O_TL;
    float* td = B + O_TD;
    float* wt = B + O_WT;
    float* t1 = B + O_T1;
    float* la = B + O_LA;
    __half* hp16 = (__half*)(B + O_HP16);
    __half* tl16 = (__half*)(B + O_TL16);
    __half* td16 = (__half*)(B + O_TD16);
    float* da[2] = {B + O_DA0, B + O_DA1};
    float* sm = B + O_SM;
    float* sq = B + O_SQ;
    int* cnt_all = (int*)(B + O_CL);
    int* off_all = (int*)(B + O_OFF);
    int* cur_all = (int*)(B + O_CUR);
    int* part    = (int*)(B + O_PART);
    int* adj_all = (int*)(B + O_ADJ);

    int* cl  = cnt_all;
    int* cd  = cnt_all + NLAB;
    int* cp1 = cnt_all + NLAB + NDIS;
    int* cp2 = cnt_all + NLAB + NDIS + NPAT;
    int* loff = off_all;
    int* doff = off_all + NLAB;
    int* p1o  = off_all + NLAB + NDIS;
    int* p2o  = off_all + NLAB + NDIS + NPAT;
    int* lcur = cur_all;
    int* dcur = cur_all + NLAB;
    int* p1c  = cur_all + NLAB + NDIS;
    int* p2c  = cur_all + NLAB + NDIS + NPAT;

    cudaFuncSetAttribute(k_gemm, cudaFuncAttributeMaxDynamicSharedMemorySize, 65536);

    // ---- streams + events (created once; never destroyed — capture-safe) ----
    static cudaStream_t sB = nullptr, sC = nullptr;
    static cudaEvent_t evRoot, evCSR, evE, evTD0, evTD1, evG0, evG1, evGP0, evHP0, evBfin;
    if (!sB) {
        cudaStreamCreateWithFlags(&sB, cudaStreamNonBlocking);
        cudaStreamCreateWithFlags(&sC, cudaStreamNonBlocking);
        cudaEventCreateWithFlags(&evRoot, cudaEventDisableTiming);
        cudaEventCreateWithFlags(&evCSR,  cudaEventDisableTiming);
        cudaEventCreateWithFlags(&evE,    cudaEventDisableTiming);
        cudaEventCreateWithFlags(&evTD0,  cudaEventDisableTiming);
        cudaEventCreateWithFlags(&evTD1,  cudaEventDisableTiming);
        cudaEventCreateWithFlags(&evG0,   cudaEventDisableTiming);
        cudaEventCreateWithFlags(&evG1,   cudaEventDisableTiming);
        cudaEventCreateWithFlags(&evGP0,  cudaEventDisableTiming);
        cudaEventCreateWithFlags(&evHP0,  cudaEventDisableTiming);
        cudaEventCreateWithFlags(&evBfin, cudaEventDisableTiming);
    }

    // fork
    cudaEventRecord(evRoot, 0);
    cudaStreamWaitEvent(sC, evRoot, 0);
    cudaStreamWaitEvent(sB, evRoot, 0);

    // ---- stream C: zero + CSR build ----
    k_zero4<<<(int)((Z_N4 + 255) / 256), 256, 0, sC>>>((float4*)(B + O_DA0), Z_N4);
    k_count<<<4096, 256, 0, sC>>>(s1, d1, NE1, cp1, cl);
    k_count<<<1024, 256, 0, sC>>>(s2, d2, NE2, cp2, cd);
    k_psum<<<SNB, 256, 0, sC>>>(cnt_all, part);
    k_scanpart<<<1, 256, 0, sC>>>(part, off_all + NTOTI);
    k_scanfinal<<<SNB, 256, 0, sC>>>(cnt_all, part, off_all, cur_all);
    k_fill<<<4096, 256, 0, sC>>>(s1, d1, NE1, lcur, p1c, adj_all);
    k_fill<<<1024, 256, 0, sC>>>(s2, d2, NE2, dcur, p2c, adj_all);
    cudaEventRecord(evCSR, sC);

    // ---- stream A (0): patient embedding ----
    k_embed_pat<<<2048, 128>>>(x_pat, Wp, bp, hp[0], hp16);
    cudaEventRecord(evE, 0);

    // ---- stream B: lab/dis embeddings + layer-0 lab/dis pipeline ----
    k_embed_lab<<<(int)((SZ_HL + 255) / 256), 256, 0, sB>>>(x_lab, Wlab, blab, hl[0]);
    k_embed_dis<<<(int)((SZ_HD + 255) / 256), 256, 0, sB>>>(x_dis, Wdis, bdis, hd[0]);
    // reverse-source pre-transforms
    k_gemm<<<444, 128, 65536, sB>>>(hl[0], Wl[0] + 2 * HH, nullptr, tl, tl16, NLAB, 0);
    k_gemm<<<63, 128, 65536, sB>>>(hd[0], Wl[0] + 3 * HH, nullptr, td, td16, NDIS, 0);
    cudaEventRecord(evTD0, sB);
    // gathers (need CSR + hp16 from embed)
    cudaStreamWaitEvent(sB, evE, 0);
    cudaStreamWaitEvent(sB, evCSR, 0);
    k_gather_mean<<<(NLAB * 32 + 255) / 256, 256, 0, sB>>>(loff, adj_all, hp16, la, NLAB);
    k_gather_mean_w8<<<(NDIS * 8 * 32 + 255) / 256, 256, 0, sB>>>(doff, adj_all, hp16, da[0], NDIS);
    cudaEventRecord(evG0, sB);
    // lab/dis updates + BN
    k_gemm<<<444, 128, 65536, sB>>>(la, Wl[0], bl[0], hl[1], nullptr, NLAB, 0);
    k_gemm<<<444, 128, 65536, sB>>>(hl[0], Wr[0], nullptr, hl[1], nullptr, NLAB, GF_ACC);
    k_stats<<<1024, 128, 0, sB>>>(hl[1], NLAB, sm + 1 * H, sq + 1 * H);
    k_bn<<<2048, 256, 0, sB>>>(hl[1], nullptr, SZ_HL, 1.f / NLAB, sm + 1 * H, sq + 1 * H,
                               bng[0] + 1 * H, bnb[0] + 1 * H);
    k_gemm<<<63, 128, 65536, sB>>>(da[0], Wl[0] + HH, bl[0] + H, hd[1], nullptr, NDIS, 0);
    k_gemm<<<63, 128, 65536, sB>>>(hd[0], Wr[0] + HH, nullptr, hd[1], nullptr, NDIS, GF_ACC);
    k_stats<<<500, 128, 0, sB>>>(hd[1], NDIS, sm + 2 * H, sq + 2 * H);
    k_bn<<<256, 256, 0, sB>>>(hd[1], nullptr, SZ_HD, 1.f / NDIS, sm + 2 * H, sq + 2 * H,
                              bng[0] + 2 * H, bnb[0] + 2 * H);

    // ---- stream A: layer-0 patient pipeline ----
    k_addw<<<(HH + 255) / 256, 256>>>(Wr[0] + 2 * HH, Wr[0] + 3 * HH, wt);
    k_gemm<<<444, 128, 65536>>>(hp[0], wt, nullptr, hp[1], nullptr, NPAT, 0);
    cudaStreamWaitEvent(0, evCSR, 0);
    cudaStreamWaitEvent(0, evTD0, 0);
    k_gather_pat<<<(NPAT * 32 + 255) / 256, 256>>>(p1o, adj_all, tl16, p2o, adj_all, td16,
                                                   bl[0] + 2 * H, bl[0] + 3 * H, hp[1]);
    cudaEventRecord(evGP0, 0);   // tl16/td16 free for reuse
    k_stats<<<1024, 128>>>(hp[1], NPAT, sm + 0 * H, sq + 0 * H);
    cudaStreamWaitEvent(0, evG0, 0);   // hp16 (layer-0) fully consumed by B's gathers
    k_bn<<<8192, 256>>>(hp[1], hp16, SZ_HP, 1.f / NPAT, sm + 0 * H, sq + 0 * H,
                        bng[0] + 0 * H, bnb[0] + 0 * H);
    cudaEventRecord(evHP0, 0);   // hp16 v2 ready

    // ---- stream B: layer-1 lab/dis pipeline ----
    cudaStreamWaitEvent(sB, evGP0, 0);  // tl16/td16 anti-dependency
    k_gemm<<<444, 128, 65536, sB>>>(hl[1], Wl[1] + 2 * HH, nullptr, tl, tl16, NLAB, 0);
    k_gemm<<<63, 128, 65536, sB>>>(hd[1], Wl[1] + 3 * HH, nullptr, td, td16, NDIS, 0);
    cudaEventRecord(evTD1, sB);
    cudaStreamWaitEvent(sB, evHP0, 0);  // hp16 v2
    k_gather_mean<<<(NLAB * 32 + 255) / 256, 256, 0, sB>>>(loff, adj_all, hp16, la, NLAB);
    k_gather_mean_w8<<<(NDIS * 8 * 32 + 255) / 256, 256, 0, sB>>>(doff, adj_all, hp16, da[1], NDIS);
    cudaEventRecord(evG1, sB);
    k_gemm<<<444, 128, 65536, sB>>>(la, Wl[1], bl[1], hl[0], nullptr, NLAB, 0);
    k_gemm<<<444, 128, 65536, sB>>>(hl[1], Wr[1], nullptr, hl[0], nullptr, NLAB, GF_ACC);
    k_stats<<<1024, 128, 0, sB>>>(hl[0], NLAB, sm + 4 * H, sq + 4 * H);
    k_bn<<<2048, 256, 0, sB>>>(hl[0], nullptr, SZ_HL, 1.f / NLAB, sm + 4 * H, sq + 4 * H,
                               bng[1] + 1 * H, bnb[1] + 1 * H);
    k_gemm<<<63, 128, 65536, sB>>>(da[1], Wl[1] + HH, bl[1] + H, hd[0], nullptr, NDIS, 0);
    k_gemm<<<63, 128, 65536, sB>>>(hd[1], Wr[1] + HH, nullptr, hd[0], nullptr, NDIS, GF_ACC);
    k_stats<<<500, 128, 0, sB>>>(hd[0], NDIS, sm + 5 * H, sq + 5 * H);
    k_bn<<<256, 256, 0, sB>>>(hd[0], nullptr, SZ_HD, 1.f / NDIS, sm + 5 * H, sq + 5 * H,
                              bng[1] + 2 * H, bnb[1] + 2 * H);
    cudaEventRecord(evBfin, sB);

    // ---- stream A: layer-1 patient pipeline + head ----
    k_addw<<<(HH + 255) / 256, 256>>>(Wr[1] + 2 * HH, Wr[1] + 3 * HH, wt);
    k_gemm<<<444, 128, 65536>>>(hp[1], wt, nullptr, hp[0], nullptr, NPAT, 0);
    cudaStreamWaitEvent(0, evTD1, 0);
    k_gather_pat<<<(NPAT * 32 + 255) / 256, 256>>>(p1o, adj_all, tl16, p2o, adj_all, td16,
                                                   bl[1] + 2 * H, bl[1] + 3 * H, hp[0]);
    k_stats<<<1024, 128>>>(hp[0], NPAT, sm + 3 * H, sq + 3 * H);
    k_bn<<<8192, 256>>>(hp[0], nullptr, SZ_HP, 1.f / NPAT, sm + 3 * H, sq + 3 * H,
                        bng[1] + 0 * H, bnb[1] + 0 * H);
    k_gemm<<<888, 64, 32768>>>(hp[0], fc1W, fc1b, t1, nullptr, NPAT, GF_RELU);
    k_head<<<(NPAT + 3) / 4, 128>>>(t1, fc2W, fc2b, (float*)d_out);

    // join side streams into the capture origin
    cudaStreamWaitEvent(0, evBfin, 0);
}

// round 15
// speedup vs baseline: 1.0019x; 1.0019x over previous
#include <cuda_runtime.h>
#include <cuda_fp16.h>
#include <math.h>

#define NPAT 100000
#define NLAB 10000
#define NDIS 500
#define NE1  2000000
#define NE2  500000
#define H    128
#define HH   (128*128)
#define FC1C 64
#define NOUT 10
#define EPSBN 1e-5f

#define NTOTI (NLAB + NDIS + NPAT + NPAT)
#define STILE 1024
#define SNB   ((NTOTI + STILE - 1) / STILE)

// ---------------- scratch layout ----------------
constexpr long SZ_HP = (long)NPAT * H;
constexpr long SZ_HL = (long)NLAB * H;
constexpr long SZ_HD = (long)NDIS * H;

constexpr long O_HP0 = 0;
constexpr long O_HP1 = O_HP0 + SZ_HP;
constexpr long O_HL0 = O_HP1 + SZ_HP;
constexpr long O_HL1 = O_HL0 + SZ_HL;
constexpr long O_HD0 = O_HL1 + SZ_HL;
constexpr long O_HD1 = O_HD0 + SZ_HD;
constexpr long O_TL  = O_HD1 + SZ_HD;
constexpr long O_TD  = O_TL + SZ_HL;
constexpr long O_WT  = O_TD + SZ_HD;
constexpr long O_T1  = O_WT + HH;
constexpr long O_LA  = O_T1 + (long)NPAT * FC1C;
constexpr long O_HP16 = O_LA + SZ_HL;
constexpr long O_TL16 = O_HP16 + SZ_HP / 2;
constexpr long O_TD16 = O_TL16 + SZ_HL / 2;
// --- zero-once region: da0 | da1 | sm[6H] | sq[6H] | counts[NTOTI] ---
constexpr long O_DA0 = O_TD16 + SZ_HD / 2;
constexpr long O_DA1 = O_DA0 + SZ_HD;
constexpr long O_SM  = O_DA1 + SZ_HD;          // 6 slots of H
constexpr long O_SQ  = O_SM + 6 * H;
constexpr long O_CL  = O_SQ + 6 * H;           // combined counts [NTOTI]
constexpr long O_OFF = O_CL + NTOTI;           // CSR offsets [NTOTI+1]
constexpr long O_CUR = O_OFF + NTOTI + 4;
constexpr long O_PART= O_CUR + NTOTI;
constexpr long O_ADJ = O_PART + 512;
constexpr long O_END = O_ADJ + 2L * (NE1 + NE2);

constexpr long Z_N4  = (O_OFF - O_DA0) / 4;    // startup zero span
constexpr long TOT4  = (O_END + 3) / 4;

__device__ float4 g_buf[TOT4];

// ---------------- utility kernels ----------------

__global__ void k_zero4(float4* p, long n4) {
    long i  = (long)blockIdx.x * blockDim.x + threadIdx.x;
    long st = (long)gridDim.x * blockDim.x;
    float4 z = make_float4(0.f, 0.f, 0.f, 0.f);
    for (; i < n4; i += st) p[i] = z;
}

__global__ void k_count(const int* __restrict__ src, const int* __restrict__ dst, int n,
                        int* cs, int* cd) {
    int i  = blockIdx.x * blockDim.x + threadIdx.x;
    int st = gridDim.x * blockDim.x;
    for (; i < n; i += st) {
        atomicAdd(cs + src[i], 1);
        atomicAdd(cd + dst[i], 1);
    }
}

__global__ void k_psum(const int* __restrict__ cnt, int* __restrict__ part) {
    __shared__ int wsum[8];
    int t = threadIdx.x;
    long base = (long)blockIdx.x * STILE + t * 4;
    int s = 0;
#pragma unroll
    for (int u = 0; u < 4; u++) {
        long i = base + u;
        if (i < NTOTI) s += cnt[i];
    }
#pragma unroll
    for (int o = 16; o > 0; o >>= 1) s += __shfl_xor_sync(0xffffffffu, s, o);
    if ((t & 31) == 0) wsum[t >> 5] = s;
    __syncthreads();
    if (t == 0) {
        int tot = 0;
#pragma unroll
        for (int i = 0; i < 8; i++) tot += wsum[i];
        part[blockIdx.x] = tot;
    }
}

__global__ void k_scanpart(int* __restrict__ part, int* __restrict__ off_end) {
    __shared__ int sh[256];
    int t = threadIdx.x;
    int v = (t < SNB) ? part[t] : 0;
    sh[t] = v;
    __syncthreads();
#pragma unroll
    for (int d = 1; d < 256; d <<= 1) {
        int x = (t >= d) ? sh[t - d] : 0;
        __syncthreads();
        sh[t] += x;
        __syncthreads();
    }
    if (t < SNB) part[t] = sh[t] - v;
    if (t == 255) *off_end = sh[255];
}

__global__ void k_scanfinal(const int* __restrict__ cnt, const int* __restrict__ part,
                            int* __restrict__ off, int* __restrict__ cur) {
    __shared__ int wpre[8];
    int t = threadIdx.x, lane = t & 31, w = t >> 5;
    long base = (long)blockIdx.x * STILE + t * 4;
    int v[4];
    int s = 0;
#pragma unroll
    for (int u = 0; u < 4; u++) {
        v[u] = (base + u < NTOTI) ? cnt[base + u] : 0;
        s += v[u];
    }
    int incl = s;
#pragma unroll
    for (int o = 1; o < 32; o <<= 1) {
        int x = __shfl_up_sync(0xffffffffu, incl, o);
        if (lane >= o) incl += x;
    }
    int excl = incl - s;
    if (lane == 31) wpre[w] = incl;
    __syncthreads();
    if (t == 0) {
        int run = 0;
#pragma unroll
        for (int i = 0; i < 8; i++) { int x = wpre[i]; wpre[i] = run; run += x; }
    }
    __syncthreads();
    int pre = part[blockIdx.x] + wpre[w] + excl;
#pragma unroll
    for (int u = 0; u < 4; u++) {
        if (base + u < NTOTI) { off[base + u] = pre; cur[base + u] = pre; }
        pre += v[u];
    }
}

__global__ void k_fill(const int* __restrict__ src, const int* __restrict__ dst, int n,
                       int* curd, int* curs, int* __restrict__ adj) {
    int i  = blockIdx.x * blockDim.x + threadIdx.x;
    int st = gridDim.x * blockDim.x;
    for (; i < n; i += st) {
        int s = src[i], d = dst[i];
        adj[atomicAdd(curd + d, 1)] = s;
        adj[atomicAdd(curs + s, 1)] = d;
    }
}

// ---------------- embeddings ----------------

__global__ void k_embed_pat(const float* __restrict__ x, const float* __restrict__ Wp,
                            const float* __restrict__ bp, float* __restrict__ out,
                            __half* __restrict__ out16) {
    __shared__ float Wsh[16 * H];
    __shared__ float xsh[8][16];
    int tid = threadIdx.x;
    for (int i = tid; i < 16 * H; i += 128) Wsh[i] = Wp[i];
    __syncthreads();
    float wreg[16];
#pragma unroll
    for (int k = 0; k < 16; k++) wreg[k] = Wsh[k * H + tid];
    float bb = bp[tid];
    for (long base = (long)blockIdx.x * 8; base < NPAT; base += (long)gridDim.x * 8) {
        int nr = (int)((NPAT - base) < 8 ? (NPAT - base) : 8);
        if (tid < nr * 16) xsh[tid >> 4][tid & 15] = x[base * 16 + tid];
        __syncthreads();
        for (int r = 0; r < nr; r++) {
            float acc = bb;
#pragma unroll
            for (int k = 0; k < 16; k++) acc = fmaf(xsh[r][k], wreg[k], acc);
            long o = (base + r) * H + tid;
            out[o]   = acc;
            out16[o] = __float2half_rn(acc);
        }
        __syncthreads();
    }
}

__global__ void k_embed_lab(const float* __restrict__ x, const float* __restrict__ W,
                            const float* __restrict__ b, float* __restrict__ out) {
    long idx = (long)blockIdx.x * blockDim.x + threadIdx.x;
    if (idx >= (long)NLAB * H) return;
    int i = (int)(idx >> 7), h = (int)(idx & 127);
    out[idx] = x[i] * W[h] + b[h];
}

__global__ void k_embed_dis(const float* __restrict__ x, const float* __restrict__ W,
                            const float* __restrict__ b, float* __restrict__ out) {
    long idx = (long)blockIdx.x * blockDim.x + threadIdx.x;
    if (idx >= (long)NDIS * H) return;
    int i = (int)(idx >> 7), h = (int)(idx & 127);
    out[idx] = x[2 * i] * W[h] + x[2 * i + 1] * W[H + h] + b[h];
}

// ---------------- gather aggregation (fp16 sources, fp32 accumulate) --------

__device__ __forceinline__ void red4(float* p, float4 v) {
    asm volatile("red.global.add.v4.f32 [%0], {%1,%2,%3,%4};"
                 :: "l"(p), "f"(v.x), "f"(v.y), "f"(v.z), "f"(v.w) : "memory");
}

__device__ __forceinline__ void acc8(float4& acc, uint2 u) {
    __half2 h0 = *(__half2*)&u.x;
    __half2 h1 = *(__half2*)&u.y;
    float2 f0 = __half22float2(h0);
    float2 f1 = __half22float2(h1);
    acc.x += f0.x; acc.y += f0.y; acc.z += f1.x; acc.w += f1.y;
}

__device__ __forceinline__ float4 gmean16(const int* __restrict__ off,
                                          const int* __restrict__ adj,
                                          const __half* __restrict__ src,
                                          int row, int lane) {
    int s = off[row], e = off[row + 1];
    float4 acc = make_float4(0.f, 0.f, 0.f, 0.f);
    int j = s;
    for (; j + 4 <= e; j += 4) {
        int i0 = __ldg(adj + j),     i1 = __ldg(adj + j + 1);
        int i2 = __ldg(adj + j + 2), i3 = __ldg(adj + j + 3);
        uint2 u0 = __ldg((const uint2*)(src + (size_t)i0 * H) + lane);
        uint2 u1 = __ldg((const uint2*)(src + (size_t)i1 * H) + lane);
        uint2 u2 = __ldg((const uint2*)(src + (size_t)i2 * H) + lane);
        uint2 u3 = __ldg((const uint2*)(src + (size_t)i3 * H) + lane);
        acc8(acc, u0); acc8(acc, u1); acc8(acc, u2); acc8(acc, u3);
    }
    for (; j < e; j++) {
        int i0 = __ldg(adj + j);
        uint2 u = __ldg((const uint2*)(src + (size_t)i0 * H) + lane);
        acc8(acc, u);
    }
    float r = 1.f / fmaxf((float)(e - s), 1.f);
    acc.x *= r; acc.y *= r; acc.z *= r; acc.w *= r;
    return acc;
}

__global__ void k_gather_mean(const int* __restrict__ off, const int* __restrict__ adj,
                              const __half* __restrict__ src, float* __restrict__ out,
                              int Nd) {
    int w    = (blockIdx.x * blockDim.x + threadIdx.x) >> 5;
    int lane = threadIdx.x & 31;
    if (w >= Nd) return;
    float4 m = gmean16(off, adj, src, w, lane);
    ((float4*)(out + (size_t)w * H))[lane] = m;
}

__global__ void k_gather_mean_w8(const int* __restrict__ off, const int* __restrict__ adj,
                                 const __half* __restrict__ src, float* __restrict__ out,
                                 int Nd) {
    int gw   = (blockIdx.x * blockDim.x + threadIdx.x) >> 5;
    int lane = threadIdx.x & 31;
    int row  = gw >> 3, sub = gw & 7;
    if (row >= Nd) return;
    int s = off[row], e = off[row + 1];
    float4 acc = make_float4(0.f, 0.f, 0.f, 0.f);
    int j = s + sub * 4;
    for (; j + 4 <= e; j += 32) {
        int i0 = __ldg(adj + j),     i1 = __ldg(adj + j + 1);
        int i2 = __ldg(adj + j + 2), i3 = __ldg(adj + j + 3);
        uint2 u0 = __ldg((const uint2*)(src + (size_t)i0 * H) + lane);
        uint2 u1 = __ldg((const uint2*)(src + (size_t)i1 * H) + lane);
        uint2 u2 = __ldg((const uint2*)(src + (size_t)i2 * H) + lane);
        uint2 u3 = __ldg((const uint2*)(src + (size_t)i3 * H) + lane);
        acc8(acc, u0); acc8(acc, u1); acc8(acc, u2); acc8(acc, u3);
    }
    if (j < e) {
        for (int t = j; t < e; t++) {
            int i0 = __ldg(adj + t);
            uint2 u = __ldg((const uint2*)(src + (size_t)i0 * H) + lane);
            acc8(acc, u);
        }
    }
    float r = 1.f / fmaxf((float)(e - s), 1.f);
    acc.x *= r; acc.y *= r; acc.z *= r; acc.w *= r;
    red4((float*)((float4*)(out + (size_t)row * H) + lane), acc);
}

__global__ void k_gather_pat(const int* __restrict__ off1, const int* __restrict__ adj1,
                             const __half* __restrict__ srcL,
                             const int* __restrict__ off2, const int* __restrict__ adj2,
                             const __half* __restrict__ srcD,
                             const float* __restrict__ b2, const float* __restrict__ b3,
                             float* __restrict__ out) {
    int w    = (blockIdx.x * blockDim.x + threadIdx.x) >> 5;
    int lane = threadIdx.x & 31;
    if (w >= NPAT) return;
    float4 a1 = gmean16(off1, adj1, srcL, w, lane);
    float4 a2 = gmean16(off2, adj2, srcD, w, lane);
    float4 bb2 = ((const float4*)b2)[lane];
    float4 bb3 = ((const float4*)b3)[lane];
    float4* o = (float4*)(out + (size_t)w * H) + lane;
    float4 v = *o;
    v.x += a1.x + a2.x + bb2.x + bb3.x;
    v.y += a1.y + a2.y + bb2.y + bb3.y;
    v.z += a1.z + a2.z + bb2.z + bb3.z;
    v.w += a1.w + a2.w + bb2.w + bb3.w;
    *o = v;
}

// ---------------- GEMM [N,128] @ [128,NC], 8 rows per tile ----------------
#define GF_ACC 1
#define GF_RELU 2
__global__ void __launch_bounds__(128) k_gemm(const float* __restrict__ A,
                                              const float* __restrict__ W,
                                              const float* __restrict__ bias,
                                              float* __restrict__ out,
                                              __half* __restrict__ out16,
                                              int N, int flags) {
    extern __shared__ float Wsh[];
    __shared__ float4 ashA[H];
    __shared__ float4 ashB[H];
    int NC  = blockDim.x;
    int tid = threadIdx.x;
    for (int i = tid; i < H * NC; i += NC) Wsh[i] = W[i];
    __syncthreads();
    float bb = bias ? bias[tid] : 0.f;
    for (long base = (long)blockIdx.x * 8; base < N; base += (long)gridDim.x * 8) {
        int nr = (int)(((long)N - base) < 8 ? ((long)N - base) : 8);
        for (int k = tid; k < H; k += NC) {
            const float* Ak = A + base * H + k;
            float4 va, vb;
            va.x = Ak[0];
            va.y = nr > 1 ? Ak[1 * H] : 0.f;
            va.z = nr > 2 ? Ak[2 * H] : 0.f;
            va.w = nr > 3 ? Ak[3 * H] : 0.f;
            vb.x = nr > 4 ? Ak[4 * H] : 0.f;
            vb.y = nr > 5 ? Ak[5 * H] : 0.f;
            vb.z = nr > 6 ? Ak[6 * H] : 0.f;
            vb.w = nr > 7 ? Ak[7 * H] : 0.f;
            ashA[k] = va;
            ashB[k] = vb;
        }
        __syncthreads();
        float a0 = bb, a1 = bb, a2 = bb, a3 = bb;
        float a4 = bb, a5 = bb, a6 = bb, a7 = bb;
#pragma unroll 16
        for (int k = 0; k < H; k++) {
            float4 av = ashA[k];
            float4 bv = ashB[k];
            float wv  = Wsh[k * NC + tid];
            a0 = fmaf(av.x, wv, a0);
            a1 = fmaf(av.y, wv, a1);
            a2 = fmaf(av.z, wv, a2);
            a3 = fmaf(av.w, wv, a3);
            a4 = fmaf(bv.x, wv, a4);
            a5 = fmaf(bv.y, wv, a5);
            a6 = fmaf(bv.z, wv, a6);
            a7 = fmaf(bv.w, wv, a7);
        }
        float rr[8] = {a0, a1, a2, a3, a4, a5, a6, a7};
        for (int r = 0; r < nr; r++) {
            long o  = (base + r) * NC + tid;
            float v = rr[r];
            if (flags & GF_ACC)  v += out[o];
            if (flags & GF_RELU) v = fmaxf(v, 0.f);
            out[o] = v;
            if (out16) out16[o] = __float2half_rn(v);
        }
        __syncthreads();
    }
}

__global__ void k_addw(const float* __restrict__ A, const float* __restrict__ Bm,
                       float* __restrict__ out) {
    int idx = blockIdx.x * blockDim.x + threadIdx.x;
    if (idx < HH) out[idx] = A[idx] + Bm[idx];
}

// ---------------- BatchNorm ----------------
__global__ void k_stats(const float* __restrict__ X, int N,
                        float* __restrict__ sum, float* __restrict__ sumsq) {
    int tid = threadIdx.x;
    float s = 0.f, ss = 0.f;
    for (long r = blockIdx.x; r < N; r += gridDim.x) {
        float v = X[r * H + tid];
        s += v;
        ss = fmaf(v, v, ss);
    }
    atomicAdd(sum + tid, s);
    atomicAdd(sumsq + tid, ss);
}

__global__ void k_bn(float* __restrict__ X, __half* __restrict__ X16, long n, float invN,
                     const float* __restrict__ sum, const float* __restrict__ sumsq,
                     const float* __restrict__ g, const float* __restrict__ b) {
    long idx = (long)blockIdx.x * blockDim.x + threadIdx.x;
    long st  = (long)gridDim.x * blockDim.x;
    for (; idx < n; idx += st) {
        int h   = (int)(idx & 127);
        float m = sum[h] * invN;
        float var = sumsq[h] * invN - m * m;
        float v = (X[idx] - m) * rsqrtf(var + EPSBN) * g[h] + b[h];
        v = fmaxf(v, 0.f);
        X[idx] = v;
        if (X16) X16[idx] = __float2half_rn(v);
    }
}

// ---------------- head ----------------
__global__ void k_head(const float* __restrict__ T, const float* __restrict__ W2,
                       const float* __restrict__ b2, float* __restrict__ out) {
    __shared__ float tsh[4][64];
    int w    = threadIdx.x >> 5;
    int lane = threadIdx.x & 31;
    long row = (long)blockIdx.x * 4 + w;
    if (row >= NPAT) return;
    tsh[w][lane]      = T[row * 64 + lane];
    tsh[w][lane + 32] = T[row * 64 + 32 + lane];
    __syncwarp();
    float z;
    if (lane < NOUT) {
        z = b2[lane];
#pragma unroll 8
        for (int j = 0; j < 64; j++) z = fmaf(tsh[w][j], __ldg(W2 + j * NOUT + lane), z);
    } else {
        z = -INFINITY;
    }
    float m = z;
#pragma unroll
    for (int off = 16; off > 0; off >>= 1) m = fmaxf(m, __shfl_xor_sync(0xffffffffu, m, off));
    float e = (lane < NOUT) ? __expf(z - m) : 0.f;
    float ssum = e;
#pragma unroll
    for (int off = 16; off > 0; off >>= 1) ssum += __shfl_xor_sync(0xffffffffu, ssum, off);
    float lse = m + __logf(ssum);
    if (lane < NOUT) out[row * NOUT + lane] = z - lse;
}

// ---------------- host ----------------
extern "C" void kernel_launch(void* const* d_in, const int* in_sizes, int n_in,
                              void* d_out, int out_size) {
    const float* x_pat = (const float*)d_in[0];
    const float* x_lab = (const float*)d_in[1];
    const float* x_dis = (const float*)d_in[2];
    const float* Wp    = (const float*)d_in[3];
    const float* bp    = (const float*)d_in[4];
    const float* Wlab  = (const float*)d_in[5];
    const float* blab  = (const float*)d_in[6];
    const float* Wdis  = (const float*)d_in[7];
    const float* bdis  = (const float*)d_in[8];
    const float* Wl[2] = {(const float*)d_in[9],  (const float*)d_in[12]};
    const float* bl[2] = {(const float*)d_in[10], (const float*)d_in[13]};
    const float* Wr[2] = {(const float*)d_in[11], (const float*)d_in[14]};
    const float* bng[2] = {(const float*)d_in[15], (const float*)d_in[17]};
    const float* bnb[2] = {(const float*)d_in[16], (const float*)d_in[18]};
    const float* fc1W  = (const float*)d_in[19];
    const float* fc1b  = (const float*)d_in[20];
    const float* fc2W  = (const float*)d_in[21];
    const float* fc2b  = (const float*)d_in[22];
    const int* s1 = (const int*)d_in[23];
    const int* d1 = (const int*)d_in[24];
    const int* s2 = (const int*)d_in[25];
    const int* d2 = (const int*)d_in[26];

    float* B = nullptr;
    cudaGetSymbolAddress((void**)&B, g_buf);

    float* hp[2] = {B + O_HP0, B + O_HP1};
    float* hl[2] = {B + O_HL0, B + O_HL1};
    float* hd[2] = {B + O_HD0, B + O_HD1};
    float* tl = B + O_TL;
    float* td = B + O_TD;
    float* wt = B + O_WT;
    float* t1 = B + O_T1;
    float* la = B + O_LA;
    __half* hp16 = (__half*)(B + O_HP16);
    __half* tl16 = (__half*)(B + O_TL16);
    __half* td16 = (__half*)(B + O_TD16);
    float* da[2] = {B + O_DA0, B + O_DA1};
    float* sm = B + O_SM;
    float* sq = B + O_SQ;
    int* cnt_all = (int*)(B + O_CL);
    int* off_all = (int*)(B + O_OFF);
    int* cur_all = (int*)(B + O_CUR);
    int* part    = (int*)(B + O_PART);
    int* adj_all = (int*)(B + O_ADJ);

    int* cl  = cnt_all;
    int* cd  = cnt_all + NLAB;
    int* cp1 = cnt_all + NLAB + NDIS;
    int* cp2 = cnt_all + NLAB + NDIS + NPAT;
    int* loff = off_all;
    int* doff = off_all + NLAB;
    int* p1o  = off_all + NLAB + NDIS;
    int* p2o  = off_all + NLAB + NDIS + NPAT;
    int* lcur = cur_all;
    int* dcur = cur_all + NLAB;
    int* p1c  = cur_all + NLAB + NDIS;
    int* p2c  = cur_all + NLAB + NDIS + NPAT;

    cudaFuncSetAttribute(k_gemm, cudaFuncAttributeMaxDynamicSharedMemorySize, 65536);

    // ---- streams + events (created once; never destroyed — capture-safe) ----
    static cudaStream_t sB = nullptr, sC = nullptr;
    static cudaEvent_t evRoot, evCSR, evE, evTD0, evTD1, evG0, evG1, evGP0, evHP0, evBfin;
    if (!sB) {
        cudaStreamCreateWithFlags(&sB, cudaStreamNonBlocking);
        cudaStreamCreateWithFlags(&sC, cudaStreamNonBlocking);
        cudaEventCreateWithFlags(&evRoot, cudaEventDisableTiming);
        cudaEventCreateWithFlags(&evCSR,  cudaEventDisableTiming);
        cudaEventCreateWithFlags(&evE,    cudaEventDisableTiming);
        cudaEventCreateWithFlags(&evTD0,  cudaEventDisableTiming);
        cudaEventCreateWithFlags(&evTD1,  cudaEventDisableTiming);
        cudaEventCreateWithFlags(&evG0,   cudaEventDisableTiming);
        cudaEventCreateWithFlags(&evG1,   cudaEventDisableTiming);
        cudaEventCreateWithFlags(&evGP0,  cudaEventDisableTiming);
        cudaEventCreateWithFlags(&evHP0,  cudaEventDisableTiming);
        cudaEventCreateWithFlags(&evBfin, cudaEventDisableTiming);
    }

    // fork
    cudaEventRecord(evRoot, 0);
    cudaStreamWaitEvent(sC, evRoot, 0);
    cudaStreamWaitEvent(sB, evRoot, 0);

    // ---- stream C: zero + CSR build ----
    k_zero4<<<(int)((Z_N4 + 255) / 256), 256, 0, sC>>>((float4*)(B + O_DA0), Z_N4);
    k_count<<<4096, 256, 0, sC>>>(s1, d1, NE1, cp1, cl);
    k_count<<<1024, 256, 0, sC>>>(s2, d2, NE2, cp2, cd);
    k_psum<<<SNB, 256, 0, sC>>>(cnt_all, part);
    k_scanpart<<<1, 256, 0, sC>>>(part, off_all + NTOTI);
    k_scanfinal<<<SNB, 256, 0, sC>>>(cnt_all, part, off_all, cur_all);
    k_fill<<<4096, 256, 0, sC>>>(s1, d1, NE1, lcur, p1c, adj_all);
    k_fill<<<1024, 256, 0, sC>>>(s2, d2, NE2, dcur, p2c, adj_all);
    cudaEventRecord(evCSR, sC);

    // ---- stream A (0): patient embedding ----
    k_embed_pat<<<2048, 128>>>(x_pat, Wp, bp, hp[0], hp16);
    cudaEventRecord(evE, 0);

    // ---- stream B: lab/dis embeddings + layer-0 lab/dis pipeline ----
    k_embed_lab<<<(int)((SZ_HL + 255) / 256), 256, 0, sB>>>(x_lab, Wlab, blab, hl[0]);
    k_embed_dis<<<(int)((SZ_HD + 255) / 256), 256, 0, sB>>>(x_dis, Wdis, bdis, hd[0]);
    // reverse-source pre-transforms
    k_gemm<<<444, 128, 65536, sB>>>(hl[0], Wl[0] + 2 * HH, nullptr, tl, tl16, NLAB, 0);
    k_gemm<<<63, 128, 65536, sB>>>(hd[0], Wl[0] + 3 * HH, nullptr, td, td16, NDIS, 0);
    cudaEventRecord(evTD0, sB);
    // gathers (need CSR + hp16 from embed)
    cudaStreamWaitEvent(sB, evE, 0);
    cudaStreamWaitEvent(sB, evCSR, 0);
    k_gather_mean<<<(NLAB * 32 + 255) / 256, 256, 0, sB>>>(loff, adj_all, hp16, la, NLAB);
    k_gather_mean_w8<<<(NDIS * 8 * 32 + 255) / 256, 256, 0, sB>>>(doff, adj_all, hp16, da[0], NDIS);
    cudaEventRecord(evG0, sB);
    // lab/dis updates + BN
    k_gemm<<<444, 128, 65536, sB>>>(la, Wl[0], bl[0], hl[1], nullptr, NLAB, 0);
    k_gemm<<<444, 128, 65536, sB>>>(hl[0], Wr[0], nullptr, hl[1], nullptr, NLAB, GF_ACC);
    k_stats<<<1024, 128, 0, sB>>>(hl[1], NLAB, sm + 1 * H, sq + 1 * H);
    k_bn<<<2048, 256, 0, sB>>>(hl[1], nullptr, SZ_HL, 1.f / NLAB, sm + 1 * H, sq + 1 * H,
                               bng[0] + 1 * H, bnb[0] + 1 * H);
    k_gemm<<<63, 128, 65536, sB>>>(da[0], Wl[0] + HH, bl[0] + H, hd[1], nullptr, NDIS, 0);
    k_gemm<<<63, 128, 65536, sB>>>(hd[0], Wr[0] + HH, nullptr, hd[1], nullptr, NDIS, GF_ACC);
    k_stats<<<500, 128, 0, sB>>>(hd[1], NDIS, sm + 2 * H, sq + 2 * H);
    k_bn<<<256, 256, 0, sB>>>(hd[1], nullptr, SZ_HD, 1.f / NDIS, sm + 2 * H, sq + 2 * H,
                              bng[0] + 2 * H, bnb[0] + 2 * H);

    // ---- stream A: layer-0 patient pipeline ----
    k_addw<<<(HH + 255) / 256, 256>>>(Wr[0] + 2 * HH, Wr[0] + 3 * HH, wt);
    k_gemm<<<444, 128, 65536>>>(hp[0], wt, nullptr, hp[1], nullptr, NPAT, 0);
    cudaStreamWaitEvent(0, evCSR, 0);
    cudaStreamWaitEvent(0, evTD0, 0);
    k_gather_pat<<<(NPAT * 32 + 255) / 256, 256>>>(p1o, adj_all, tl16, p2o, adj_all, td16,
                                                   bl[0] + 2 * H, bl[0] + 3 * H, hp[1]);
    cudaEventRecord(evGP0, 0);   // tl16/td16 free for reuse
    k_stats<<<1024, 128>>>(hp[1], NPAT, sm + 0 * H, sq + 0 * H);
    cudaStreamWaitEvent(0, evG0, 0);   // hp16 (layer-0) fully consumed by B's gathers
    k_bn<<<8192, 256>>>(hp[1], hp16, SZ_HP, 1.f / NPAT, sm + 0 * H, sq + 0 * H,
                        bng[0] + 0 * H, bnb[0] + 0 * H);
    cudaEventRecord(evHP0, 0);   // hp16 v2 ready

    // ---- stream B: layer-1 lab/dis pipeline ----
    cudaStreamWaitEvent(sB, evGP0, 0);  // tl16/td16 anti-dependency
    k_gemm<<<444, 128, 65536, sB>>>(hl[1], Wl[1] + 2 * HH, nullptr, tl, tl16, NLAB, 0);
    k_gemm<<<63, 128, 65536, sB>>>(hd[1], Wl[1] + 3 * HH, nullptr, td, td16, NDIS, 0);
    cudaEventRecord(evTD1, sB);
    cudaStreamWaitEvent(sB, evHP0, 0);  // hp16 v2
    k_gather_mean<<<(NLAB * 32 + 255) / 256, 256, 0, sB>>>(loff, adj_all, hp16, la, NLAB);
    k_gather_mean_w8<<<(NDIS * 8 * 32 + 255) / 256, 256, 0, sB>>>(doff, adj_all, hp16, da[1], NDIS);
    cudaEventRecord(evG1, sB);
    k_gemm<<<444, 128, 65536, sB>>>(la, Wl[1], bl[1], hl[0], nullptr, NLAB, 0);
    k_gemm<<<444, 128, 65536, sB>>>(hl[1], Wr[1], nullptr, hl[0], nullptr, NLAB, GF_ACC);
    k_stats<<<1024, 128, 0, sB>>>(hl[0], NLAB, sm + 4 * H, sq + 4 * H);
    k_bn<<<2048, 256, 0, sB>>>(hl[0], nullptr, SZ_HL, 1.f / NLAB, sm + 4 * H, sq + 4 * H,
                               bng[1] + 1 * H, bnb[1] + 1 * H);
    k_gemm<<<63, 128, 65536, sB>>>(da[1], Wl[1] + HH, bl[1] + H, hd[0], nullptr, NDIS, 0);
    k_gemm<<<63, 128, 65536, sB>>>(hd[1], Wr[1] + HH, nullptr, hd[0], nullptr, NDIS, GF_ACC);
    k_stats<<<500, 128, 0, sB>>>(hd[0], NDIS, sm + 5 * H, sq + 5 * H);
    k_bn<<<256, 256, 0, sB>>>(hd[0], nullptr, SZ_HD, 1.f / NDIS, sm + 5 * H, sq + 5 * H,
                              bng[1] + 2 * H, bnb[1] + 2 * H);
    cudaEventRecord(evBfin, sB);

    // ---- stream A: layer-1 patient pipeline + head ----
    k_addw<<<(HH + 255) / 256, 256>>>(Wr[1] + 2 * HH, Wr[1] + 3 * HH, wt);
    k_gemm<<<444, 128, 65536>>>(hp[1], wt, nullptr, hp[0], nullptr, NPAT, 0);
    cudaStreamWaitEvent(0, evTD1, 0);
    k_gather_pat<<<(NPAT * 32 + 255) / 256, 256>>>(p1o, adj_all, tl16, p2o, adj_all, td16,
                                                   bl[1] + 2 * H, bl[1] + 3 * H, hp[0]);
    k_stats<<<1024, 128>>>(hp[0], NPAT, sm + 3 * H, sq + 3 * H);
    k_bn<<<8192, 256>>>(hp[0], nullptr, SZ_HP, 1.f / NPAT, sm + 3 * H, sq + 3 * H,
                        bng[1] + 0 * H, bnb[1] + 0 * H);
    k_gemm<<<888, 64, 32768>>>(hp[0], fc1W, fc1b, t1, nullptr, NPAT, GF_RELU);
    k_head<<<(NPAT + 3) / 4, 128>>>(t1, fc2W, fc2b, (float*)d_out);

    // join side streams into the capture origin
    cudaStreamWaitEvent(0, evBfin, 0);
}

// round 16
// speedup vs baseline: 1.1203x; 1.1182x over previous
#include <cuda_runtime.h>
#include <cuda_fp16.h>
#include <math.h>

#define NPAT 100000
#define NLAB 10000
#define NDIS 500
#define NE1  2000000
#define NE2  500000
#define H    128
#define HH   (128*128)
#define FC1C 64
#define NOUT 10
#define EPSBN 1e-5f

#define NTOTI (NLAB + NDIS + NPAT + NPAT)
#define STILE 1024
#define SNB   ((NTOTI + STILE - 1) / STILE)

// ---------------- scratch layout ----------------
constexpr long SZ_HP = (long)NPAT * H;
constexpr long SZ_HL = (long)NLAB * H;
constexpr long SZ_HD = (long)NDIS * H;

constexpr long O_HP0 = 0;
constexpr long O_HP1 = O_HP0 + SZ_HP;
constexpr long O_HL0 = O_HP1 + SZ_HP;
constexpr long O_HL1 = O_HL0 + SZ_HL;
constexpr long O_HD0 = O_HL1 + SZ_HL;
constexpr long O_HD1 = O_HD0 + SZ_HD;
constexpr long O_TL  = O_HD1 + SZ_HD;
constexpr long O_TD  = O_TL + SZ_HL;
constexpr long O_WT  = O_TD + SZ_HD;          // wt16 lives here (fp16)
constexpr long O_T1  = O_WT + HH;
constexpr long O_LA  = O_T1 + (long)NPAT * FC1C;
constexpr long O_HP16 = O_LA + SZ_HL;
constexpr long O_TL16 = O_HP16 + SZ_HP / 2;
constexpr long O_TD16 = O_TL16 + SZ_HL / 2;
// --- zero-once region: da0 | da1 | sm[6H] | sq[6H] | counts[NTOTI] ---
constexpr long O_DA0 = O_TD16 + SZ_HD / 2;
constexpr long O_DA1 = O_DA0 + SZ_HD;
constexpr long O_SM  = O_DA1 + SZ_HD;
constexpr long O_SQ  = O_SM + 6 * H;
constexpr long O_CL  = O_SQ + 6 * H;
constexpr long O_OFF = O_CL + NTOTI;
constexpr long O_CUR = O_OFF + NTOTI + 4;
constexpr long O_PART= O_CUR + NTOTI;
constexpr long O_ADJ = O_PART + 512;
constexpr long O_END = O_ADJ + 2L * (NE1 + NE2);

constexpr long Z_N4  = (O_OFF - O_DA0) / 4;
constexpr long TOT4  = (O_END + 3) / 4;

__device__ float4 g_buf[TOT4];

// ---------------- utility kernels ----------------

__global__ void k_zero4(float4* p, long n4) {
    long i  = (long)blockIdx.x * blockDim.x + threadIdx.x;
    long st = (long)gridDim.x * blockDim.x;
    float4 z = make_float4(0.f, 0.f, 0.f, 0.f);
    for (; i < n4; i += st) p[i] = z;
}

__global__ void k_count(const int* __restrict__ src, const int* __restrict__ dst, int n,
                        int* cs, int* cd) {
    int i  = blockIdx.x * blockDim.x + threadIdx.x;
    int st = gridDim.x * blockDim.x;
    for (; i < n; i += st) {
        atomicAdd(cs + src[i], 1);
        atomicAdd(cd + dst[i], 1);
    }
}

__global__ void k_psum(const int* __restrict__ cnt, int* __restrict__ part) {
    __shared__ int wsum[8];
    int t = threadIdx.x;
    long base = (long)blockIdx.x * STILE + t * 4;
    int s = 0;
#pragma unroll
    for (int u = 0; u < 4; u++) {
        long i = base + u;
        if (i < NTOTI) s += cnt[i];
    }
#pragma unroll
    for (int o = 16; o > 0; o >>= 1) s += __shfl_xor_sync(0xffffffffu, s, o);
    if ((t & 31) == 0) wsum[t >> 5] = s;
    __syncthreads();
    if (t == 0) {
        int tot = 0;
#pragma unroll
        for (int i = 0; i < 8; i++) tot += wsum[i];
        part[blockIdx.x] = tot;
    }
}

__global__ void k_scanpart(int* __restrict__ part, int* __restrict__ off_end) {
    __shared__ int sh[256];
    int t = threadIdx.x;
    int v = (t < SNB) ? part[t] : 0;
    sh[t] = v;
    __syncthreads();
#pragma unroll
    for (int d = 1; d < 256; d <<= 1) {
        int x = (t >= d) ? sh[t - d] : 0;
        __syncthreads();
        sh[t] += x;
        __syncthreads();
    }
    if (t < SNB) part[t] = sh[t] - v;
    if (t == 255) *off_end = sh[255];
}

__global__ void k_scanfinal(const int* __restrict__ cnt, const int* __restrict__ part,
                            int* __restrict__ off, int* __restrict__ cur) {
    __shared__ int wpre[8];
    int t = threadIdx.x, lane = t & 31, w = t >> 5;
    long base = (long)blockIdx.x * STILE + t * 4;
    int v[4];
    int s = 0;
#pragma unroll
    for (int u = 0; u < 4; u++) {
        v[u] = (base + u < NTOTI) ? cnt[base + u] : 0;
        s += v[u];
    }
    int incl = s;
#pragma unroll
    for (int o = 1; o < 32; o <<= 1) {
        int x = __shfl_up_sync(0xffffffffu, incl, o);
        if (lane >= o) incl += x;
    }
    int excl = incl - s;
    if (lane == 31) wpre[w] = incl;
    __syncthreads();
    if (t == 0) {
        int run = 0;
#pragma unroll
        for (int i = 0; i < 8; i++) { int x = wpre[i]; wpre[i] = run; run += x; }
    }
    __syncthreads();
    int pre = part[blockIdx.x] + wpre[w] + excl;
#pragma unroll
    for (int u = 0; u < 4; u++) {
        if (base + u < NTOTI) { off[base + u] = pre; cur[base + u] = pre; }
        pre += v[u];
    }
}

__global__ void k_fill(const int* __restrict__ src, const int* __restrict__ dst, int n,
                       int* curd, int* curs, int* __restrict__ adj) {
    int i  = blockIdx.x * blockDim.x + threadIdx.x;
    int st = gridDim.x * blockDim.x;
    for (; i < n; i += st) {
        int s = src[i], d = dst[i];
        adj[atomicAdd(curd + d, 1)] = s;
        adj[atomicAdd(curs + s, 1)] = d;
    }
}

// ---------------- embeddings ----------------

__global__ void k_embed_pat(const float* __restrict__ x, const float* __restrict__ Wp,
                            const float* __restrict__ bp, float* __restrict__ out,
                            __half* __restrict__ out16) {
    __shared__ float Wsh[16 * H];
    __shared__ float xsh[8][16];
    int tid = threadIdx.x;
    for (int i = tid; i < 16 * H; i += 128) Wsh[i] = Wp[i];
    __syncthreads();
    float wreg[16];
#pragma unroll
    for (int k = 0; k < 16; k++) wreg[k] = Wsh[k * H + tid];
    float bb = bp[tid];
    for (long base = (long)blockIdx.x * 8; base < NPAT; base += (long)gridDim.x * 8) {
        int nr = (int)((NPAT - base) < 8 ? (NPAT - base) : 8);
        if (tid < nr * 16) xsh[tid >> 4][tid & 15] = x[base * 16 + tid];
        __syncthreads();
        for (int r = 0; r < nr; r++) {
            float acc = bb;
#pragma unroll
            for (int k = 0; k < 16; k++) acc = fmaf(xsh[r][k], wreg[k], acc);
            long o = (base + r) * H + tid;
            out[o]   = acc;
            out16[o] = __float2half_rn(acc);
        }
        __syncthreads();
    }
}

__global__ void k_embed_lab(const float* __restrict__ x, const float* __restrict__ W,
                            const float* __restrict__ b, float* __restrict__ out) {
    long idx = (long)blockIdx.x * blockDim.x + threadIdx.x;
    if (idx >= (long)NLAB * H) return;
    int i = (int)(idx >> 7), h = (int)(idx & 127);
    out[idx] = x[i] * W[h] + b[h];
}

__global__ void k_embed_dis(const float* __restrict__ x, const float* __restrict__ W,
                            const float* __restrict__ b, float* __restrict__ out) {
    long idx = (long)blockIdx.x * blockDim.x + threadIdx.x;
    if (idx >= (long)NDIS * H) return;
    int i = (int)(idx >> 7), h = (int)(idx & 127);
    out[idx] = x[2 * i] * W[h] + x[2 * i + 1] * W[H + h] + b[h];
}

// ---------------- gather aggregation (fp16 sources, fp32 accumulate) --------

__device__ __forceinline__ void red4(float* p, float4 v) {
    asm volatile("red.global.add.v4.f32 [%0], {%1,%2,%3,%4};"
                 :: "l"(p), "f"(v.x), "f"(v.y), "f"(v.z), "f"(v.w) : "memory");
}

__device__ __forceinline__ void acc8(float4& acc, uint2 u) {
    __half2 h0 = *(__half2*)&u.x;
    __half2 h1 = *(__half2*)&u.y;
    float2 f0 = __half22float2(h0);
    float2 f1 = __half22float2(h1);
    acc.x += f0.x; acc.y += f0.y; acc.z += f1.x; acc.w += f1.y;
}

__device__ __forceinline__ float4 gmean16(const int* __restrict__ off,
                                          const int* __restrict__ adj,
                                          const __half* __restrict__ src,
                                          int row, int lane) {
    int s = off[row], e = off[row + 1];
    float4 acc = make_float4(0.f, 0.f, 0.f, 0.f);
    int j = s;
    for (; j + 4 <= e; j += 4) {
        int i0 = __ldg(adj + j),     i1 = __ldg(adj + j + 1);
        int i2 = __ldg(adj + j + 2), i3 = __ldg(adj + j + 3);
        uint2 u0 = __ldg((const uint2*)(src + (size_t)i0 * H) + lane);
        uint2 u1 = __ldg((const uint2*)(src + (size_t)i1 * H) + lane);
        uint2 u2 = __ldg((const uint2*)(src + (size_t)i2 * H) + lane);
        uint2 u3 = __ldg((const uint2*)(src + (size_t)i3 * H) + lane);
        acc8(acc, u0); acc8(acc, u1); acc8(acc, u2); acc8(acc, u3);
    }
    for (; j < e; j++) {
        int i0 = __ldg(adj + j);
        uint2 u = __ldg((const uint2*)(src + (size_t)i0 * H) + lane);
        acc8(acc, u);
    }
    float r = 1.f / fmaxf((float)(e - s), 1.f);
    acc.x *= r; acc.y *= r; acc.z *= r; acc.w *= r;
    return acc;
}

__global__ void k_gather_mean(const int* __restrict__ off, const int* __restrict__ adj,
                              const __half* __restrict__ src, float* __restrict__ out,
                              int Nd) {
    int w    = (blockIdx.x * blockDim.x + threadIdx.x) >> 5;
    int lane = threadIdx.x & 31;
    if (w >= Nd) return;
    float4 m = gmean16(off, adj, src, w, lane);
    ((float4*)(out + (size_t)w * H))[lane] = m;
}

__global__ void k_gather_mean_w8(const int* __restrict__ off, const int* __restrict__ adj,
                                 const __half* __restrict__ src, float* __restrict__ out,
                                 int Nd) {
    int gw   = (blockIdx.x * blockDim.x + threadIdx.x) >> 5;
    int lane = threadIdx.x & 31;
    int row  = gw >> 3, sub = gw & 7;
    if (row >= Nd) return;
    int s = off[row], e = off[row + 1];
    float4 acc = make_float4(0.f, 0.f, 0.f, 0.f);
    int j = s + sub * 4;
    for (; j + 4 <= e; j += 32) {
        int i0 = __ldg(adj + j),     i1 = __ldg(adj + j + 1);
        int i2 = __ldg(adj + j + 2), i3 = __ldg(adj + j + 3);
        uint2 u0 = __ldg((const uint2*)(src + (size_t)i0 * H) + lane);
        uint2 u1 = __ldg((const uint2*)(src + (size_t)i1 * H) + lane);
        uint2 u2 = __ldg((const uint2*)(src + (size_t)i2 * H) + lane);
        uint2 u3 = __ldg((const uint2*)(src + (size_t)i3 * H) + lane);
        acc8(acc, u0); acc8(acc, u1); acc8(acc, u2); acc8(acc, u3);
    }
    if (j < e) {
        for (int t = j; t < e; t++) {
            int i0 = __ldg(adj + t);
            uint2 u = __ldg((const uint2*)(src + (size_t)i0 * H) + lane);
            acc8(acc, u);
        }
    }
    float r = 1.f / fmaxf((float)(e - s), 1.f);
    acc.x *= r; acc.y *= r; acc.z *= r; acc.w *= r;
    red4((float*)((float4*)(out + (size_t)row * H) + lane), acc);
}

// patients: out += means + biases, fused BN column stats (grid exactly NPAT warps)
__global__ void k_gather_pat(const int* __restrict__ off1, const int* __restrict__ adj1,
                             const __half* __restrict__ srcL,
                             const int* __restrict__ off2, const int* __restrict__ adj2,
                             const __half* __restrict__ srcD,
                             const float* __restrict__ b2, const float* __restrict__ b3,
                             float* __restrict__ out,
                             float* __restrict__ gsum, float* __restrict__ gsq) {
    __shared__ float bsum[H], bsq[H];
    int tid  = threadIdx.x;
    if (tid < H) { bsum[tid] = 0.f; bsq[tid] = 0.f; }
    __syncthreads();
    int w    = (blockIdx.x * blockDim.x + tid) >> 5;
    int lane = tid & 31;
    float4 a1 = gmean16(off1, adj1, srcL, w, lane);
    float4 a2 = gmean16(off2, adj2, srcD, w, lane);
    float4 bb2 = ((const float4*)b2)[lane];
    float4 bb3 = ((const float4*)b3)[lane];
    float4* o = (float4*)(out + (size_t)w * H) + lane;
    float4 v = *o;
    v.x += a1.x + a2.x + bb2.x + bb3.x;
    v.y += a1.y + a2.y + bb2.y + bb3.y;
    v.z += a1.z + a2.z + bb2.z + bb3.z;
    v.w += a1.w + a2.w + bb2.w + bb3.w;
    *o = v;
    int c = lane * 4;
    atomicAdd(bsum + c + 0, v.x); atomicAdd(bsq + c + 0, v.x * v.x);
    atomicAdd(bsum + c + 1, v.y); atomicAdd(bsq + c + 1, v.y * v.y);
    atomicAdd(bsum + c + 2, v.z); atomicAdd(bsq + c + 2, v.z * v.z);
    atomicAdd(bsum + c + 3, v.w); atomicAdd(bsq + c + 3, v.w * v.w);
    __syncthreads();
    if (tid < H) {
        atomicAdd(gsum + tid, bsum[tid]);
        atomicAdd(gsq + tid, bsq[tid]);
    }
}

// ---------------- fp16 tensor-core GEMM: out[N,128] = A16[N,128] @ W16[128,128] ----
// block = 128 threads (4 warps); 64-row tiles; W staged once per block.
#define MMA_SMEM (128 * 272 + 64 * 272)
__global__ void __launch_bounds__(128) k_mma(const __half* __restrict__ A16,
                                             const __half* __restrict__ W16,
                                             float* __restrict__ out, int N) {
    extern __shared__ char smem[];
    __half* Wsh = (__half*)smem;                  // 128 rows x 136 halves (272 B)
    __half* Ash = (__half*)(smem + 128 * 272);    // 64 rows x 136 halves
    unsigned Wbase = (unsigned)__cvta_generic_to_shared(Wsh);
    unsigned Abase = (unsigned)__cvta_generic_to_shared(Ash);
    int tid = threadIdx.x, lane = tid & 31, w = tid >> 5;

    // stage W: 128x128 halves = 8192 uint32
    {
        const unsigned* src = (const unsigned*)W16;
        unsigned* dst = (unsigned*)Wsh;
        for (int i = tid; i < 8192; i += 128) {
            int r = i >> 6, c = i & 63;
            dst[r * 68 + c] = src[i];
        }
    }

    int arow  = w * 16 + (lane & 7) + ((lane >> 3) & 1) * 8;
    int acolb = ((lane >> 4) & 1) * 16;
    int brow  = lane & 15;

    int ntiles = (N + 63) >> 6;
    for (int t = blockIdx.x; t < ntiles; t += gridDim.x) {
        long base = (long)t * 64;
        __syncthreads();   // W ready (first iter) / previous tile's mma done
        {
            const uint2* srcA = (const uint2*)A16;
            uint2* dstA = (uint2*)Ash;
            for (int i = tid; i < 2048; i += 128) {
                int r = i >> 5, c = i & 31;
                long gr = base + r;
                uint2 vv = (gr < N) ? srcA[gr * 32 + c] : make_uint2(0u, 0u);
                dstA[r * 34 + c] = vv;
            }
        }
        __syncthreads();

        float d[16][4];
#pragma unroll
        for (int nt = 0; nt < 16; nt++) {
            d[nt][0] = 0.f; d[nt][1] = 0.f; d[nt][2] = 0.f; d[nt][3] = 0.f;
        }

#pragma unroll
        for (int ks = 0; ks < 8; ks++) {
            unsigned a0, a1, a2, a3;
            unsigned aaddr = Abase + arow * 272 + ks * 32 + acolb;
            asm volatile("ldmatrix.sync.aligned.m8n8.x4.shared.b16 {%0,%1,%2,%3}, [%4];"
                         : "=r"(a0), "=r"(a1), "=r"(a2), "=r"(a3) : "r"(aaddr));
            unsigned baddr0 = Wbase + (ks * 16 + brow) * 272;
#pragma unroll
            for (int nt = 0; nt < 16; nt++) {
                unsigned b0, b1;
                asm volatile("ldmatrix.sync.aligned.m8n8.x2.trans.shared.b16 {%0,%1}, [%2];"
                             : "=r"(b0), "=r"(b1) : "r"(baddr0 + nt * 16));
                asm volatile("mma.sync.aligned.m16n8k16.row.col.f32.f16.f16.f32 "
                             "{%0,%1,%2,%3}, {%4,%5,%6,%7}, {%8,%9}, {%0,%1,%2,%3};"
                             : "+f"(d[nt][0]), "+f"(d[nt][1]), "+f"(d[nt][2]), "+f"(d[nt][3])
                             : "r"(a0), "r"(a1), "r"(a2), "r"(a3), "r"(b0), "r"(b1));
            }
        }

        int g = lane >> 2, t2 = (lane & 3) * 2;
        long r0 = base + w * 16 + g;
        long r1 = r0 + 8;
#pragma unroll
        for (int nt = 0; nt < 16; nt++) {
            int col = nt * 8 + t2;
            if (r0 < N) *(float2*)&out[r0 * H + col] = make_float2(d[nt][0], d[nt][1]);
            if (r1 < N) *(float2*)&out[r1 * H + col] = make_float2(d[nt][2], d[nt][3]);
        }
    }
}

// ---------------- fp32 GEMM (labs/diseases/fc1) ----------------
#define GF_ACC 1
#define GF_RELU 2
__global__ void __launch_bounds__(128) k_gemm(const float* __restrict__ A,
                                              const float* __restrict__ W,
                                              const float* __restrict__ bias,
                                              float* __restrict__ out,
                                              __half* __restrict__ out16,
                                              int N, int flags) {
    extern __shared__ float Wsh[];
    __shared__ float4 ashA[H];
    __shared__ float4 ashB[H];
    int NC  = blockDim.x;
    int tid = threadIdx.x;
    for (int i = tid; i < H * NC; i += NC) Wsh[i] = W[i];
    __syncthreads();
    float bb = bias ? bias[tid] : 0.f;
    for (long base = (long)blockIdx.x * 8; base < N; base += (long)gridDim.x * 8) {
        int nr = (int)(((long)N - base) < 8 ? ((long)N - base) : 8);
        for (int k = tid; k < H; k += NC) {
            const float* Ak = A + base * H + k;
            float4 va, vb;
            va.x = Ak[0];
            va.y = nr > 1 ? Ak[1 * H] : 0.f;
            va.z = nr > 2 ? Ak[2 * H] : 0.f;
            va.w = nr > 3 ? Ak[3 * H] : 0.f;
            vb.x = nr > 4 ? Ak[4 * H] : 0.f;
            vb.y = nr > 5 ? Ak[5 * H] : 0.f;
            vb.z = nr > 6 ? Ak[6 * H] : 0.f;
            vb.w = nr > 7 ? Ak[7 * H] : 0.f;
            ashA[k] = va;
            ashB[k] = vb;
        }
        __syncthreads();
        float a0 = bb, a1 = bb, a2 = bb, a3 = bb;
        float a4 = bb, a5 = bb, a6 = bb, a7 = bb;
#pragma unroll 16
        for (int k = 0; k < H; k++) {
            float4 av = ashA[k];
            float4 bv = ashB[k];
            float wv  = Wsh[k * NC + tid];
            a0 = fmaf(av.x, wv, a0);
            a1 = fmaf(av.y, wv, a1);
            a2 = fmaf(av.z, wv, a2);
            a3 = fmaf(av.w, wv, a3);
            a4 = fmaf(bv.x, wv, a4);
            a5 = fmaf(bv.y, wv, a5);
            a6 = fmaf(bv.z, wv, a6);
            a7 = fmaf(bv.w, wv, a7);
        }
        float rr[8] = {a0, a1, a2, a3, a4, a5, a6, a7};
        for (int r = 0; r < nr; r++) {
            long o  = (base + r) * NC + tid;
            float v = rr[r];
            if (flags & GF_ACC)  v += out[o];
            if (flags & GF_RELU) v = fmaxf(v, 0.f);
            out[o] = v;
            if (out16) out16[o] = __float2half_rn(v);
        }
        __syncthreads();
    }
}

__global__ void k_addw16(const float* __restrict__ A, const float* __restrict__ Bm,
                         __half* __restrict__ out) {
    int idx = blockIdx.x * blockDim.x + threadIdx.x;
    if (idx < HH) out[idx] = __float2half_rn(A[idx] + Bm[idx]);
}

// ---------------- BatchNorm ----------------
__global__ void k_stats(const float* __restrict__ X, int N,
                        float* __restrict__ sum, float* __restrict__ sumsq) {
    int tid = threadIdx.x;
    float s = 0.f, ss = 0.f;
    for (long r = blockIdx.x; r < N; r += gridDim.x) {
        float v = X[r * H + tid];
        s += v;
        ss = fmaf(v, v, ss);
    }
    atomicAdd(sum + tid, s);
    atomicAdd(sumsq + tid, ss);
}

__global__ void k_bn(float* __restrict__ X, __half* __restrict__ X16, long n, float invN,
                     const float* __restrict__ sum, const float* __restrict__ sumsq,
                     const float* __restrict__ g, const float* __restrict__ b) {
    long idx = (long)blockIdx.x * blockDim.x + threadIdx.x;
    long st  = (long)gridDim.x * blockDim.x;
    for (; idx < n; idx += st) {
        int h   = (int)(idx & 127);
        float m = sum[h] * invN;
        float var = sumsq[h] * invN - m * m;
        float v = (X[idx] - m) * rsqrtf(var + EPSBN) * g[h] + b[h];
        v = fmaxf(v, 0.f);
        X[idx] = v;
        if (X16) X16[idx] = __float2half_rn(v);
    }
}

// ---------------- head ----------------
__global__ void k_head(const float* __restrict__ T, const float* __restrict__ W2,
                       const float* __restrict__ b2, float* __restrict__ out) {
    __shared__ float tsh[4][64];
    int w    = threadIdx.x >> 5;
    int lane = threadIdx.x & 31;
    long row = (long)blockIdx.x * 4 + w;
    if (row >= NPAT) return;
    tsh[w][lane]      = T[row * 64 + lane];
    tsh[w][lane + 32] = T[row * 64 + 32 + lane];
    __syncwarp();
    float z;
    if (lane < NOUT) {
        z = b2[lane];
#pragma unroll 8
        for (int j = 0; j < 64; j++) z = fmaf(tsh[w][j], __ldg(W2 + j * NOUT + lane), z);
    } else {
        z = -INFINITY;
    }
    float m = z;
#pragma unroll
    for (int off = 16; off > 0; off >>= 1) m = fmaxf(m, __shfl_xor_sync(0xffffffffu, m, off));
    float e = (lane < NOUT) ? __expf(z - m) : 0.f;
    float ssum = e;
#pragma unroll
    for (int off = 16; off > 0; off >>= 1) ssum += __shfl_xor_sync(0xffffffffu, ssum, off);
    float lse = m + __logf(ssum);
    if (lane < NOUT) out[row * NOUT + lane] = z - lse;
}

// ---------------- host ----------------
extern "C" void kernel_launch(void* const* d_in, const int* in_sizes, int n_in,
                              void* d_out, int out_size) {
    const float* x_pat = (const float*)d_in[0];
    const float* x_lab = (const float*)d_in[1];
    const float* x_dis = (const float*)d_in[2];
    const float* Wp    = (const float*)d_in[3];
    const float* bp    = (const float*)d_in[4];
    const float* Wlab  = (const float*)d_in[5];
    const float* blab  = (const float*)d_in[6];
    const float* Wdis  = (const float*)d_in[7];
    const float* bdis  = (const float*)d_in[8];
    const float* Wl[2] = {(const float*)d_in[9],  (const float*)d_in[12]};
    const float* bl[2] = {(const float*)d_in[10], (const float*)d_in[13]};
    const float* Wr[2] = {(const float*)d_in[11], (const float*)d_in[14]};
    const float* bng[2] = {(const float*)d_in[15], (const float*)d_in[17]};
    const float* bnb[2] = {(const float*)d_in[16], (const float*)d_in[18]};
    const float* fc1W  = (const float*)d_in[19];
    const float* fc1b  = (const float*)d_in[20];
    const float* fc2W  = (const float*)d_in[21];
    const float* fc2b  = (const float*)d_in[22];
    const int* s1 = (const int*)d_in[23];
    const int* d1 = (const int*)d_in[24];
    const int* s2 = (const int*)d_in[25];
    const int* d2 = (const int*)d_in[26];

    float* B = nullptr;
    cudaGetSymbolAddress((void**)&B, g_buf);

    float* hp[2] = {B + O_HP0, B + O_HP1};
    float* hl[2] = {B + O_HL0, B + O_HL1};
    float* hd[2] = {B + O_HD0, B + O_HD1};
    float* tl = B + O_TL;
    float* td = B + O_TD;
    __half* wt16 = (__half*)(B + O_WT);
    float* t1 = B + O_T1;
    float* la = B + O_LA;
    __half* hp16 = (__half*)(B + O_HP16);
    __half* tl16 = (__half*)(B + O_TL16);
    __half* td16 = (__half*)(B + O_TD16);
    float* da[2] = {B + O_DA0, B + O_DA1};
    float* sm = B + O_SM;
    float* sq = B + O_SQ;
    int* cnt_all = (int*)(B + O_CL);
    int* off_all = (int*)(B + O_OFF);
    int* cur_all = (int*)(B + O_CUR);
    int* part    = (int*)(B + O_PART);
    int* adj_all = (int*)(B + O_ADJ);

    int* cl  = cnt_all;
    int* cd  = cnt_all + NLAB;
    int* cp1 = cnt_all + NLAB + NDIS;
    int* cp2 = cnt_all + NLAB + NDIS + NPAT;
    int* loff = off_all;
    int* doff = off_all + NLAB;
    int* p1o  = off_all + NLAB + NDIS;
    int* p2o  = off_all + NLAB + NDIS + NPAT;
    int* lcur = cur_all;
    int* dcur = cur_all + NLAB;
    int* p1c  = cur_all + NLAB + NDIS;
    int* p2c  = cur_all + NLAB + NDIS + NPAT;

    cudaFuncSetAttribute(k_gemm, cudaFuncAttributeMaxDynamicSharedMemorySize, 65536);
    cudaFuncSetAttribute(k_mma, cudaFuncAttributeMaxDynamicSharedMemorySize, MMA_SMEM);

    static cudaStream_t sB = nullptr, sC = nullptr;
    static cudaEvent_t evRoot, evCSR, evE, evTD0, evTD1, evG0, evG1, evGP0, evHP0, evBfin;
    if (!sB) {
        cudaStreamCreateWithFlags(&sB, cudaStreamNonBlocking);
        cudaStreamCreateWithFlags(&sC, cudaStreamNonBlocking);
        cudaEventCreateWithFlags(&evRoot, cudaEventDisableTiming);
        cudaEventCreateWithFlags(&evCSR,  cudaEventDisableTiming);
        cudaEventCreateWithFlags(&evE,    cudaEventDisableTiming);
        cudaEventCreateWithFlags(&evTD0,  cudaEventDisableTiming);
        cudaEventCreateWithFlags(&evTD1,  cudaEventDisableTiming);
        cudaEventCreateWithFlags(&evG0,   cudaEventDisableTiming);
        cudaEventCreateWithFlags(&evG1,   cudaEventDisableTiming);
        cudaEventCreateWithFlags(&evGP0,  cudaEventDisableTiming);
        cudaEventCreateWithFlags(&evHP0,  cudaEventDisableTiming);
        cudaEventCreateWithFlags(&evBfin, cudaEventDisableTiming);
    }

    // fork
    cudaEventRecord(evRoot, 0);
    cudaStreamWaitEvent(sC, evRoot, 0);
    cudaStreamWaitEvent(sB, evRoot, 0);

    // ---- stream C: zero + CSR build ----
    k_zero4<<<(int)((Z_N4 + 255) / 256), 256, 0, sC>>>((float4*)(B + O_DA0), Z_N4);
    k_count<<<4096, 256, 0, sC>>>(s1, d1, NE1, cp1, cl);
    k_count<<<1024, 256, 0, sC>>>(s2, d2, NE2, cp2, cd);
    k_psum<<<SNB, 256, 0, sC>>>(cnt_all, part);
    k_scanpart<<<1, 256, 0, sC>>>(part, off_all + NTOTI);
    k_scanfinal<<<SNB, 256, 0, sC>>>(cnt_all, part, off_all, cur_all);
    k_fill<<<4096, 256, 0, sC>>>(s1, d1, NE1, lcur, p1c, adj_all);
    k_fill<<<1024, 256, 0, sC>>>(s2, d2, NE2, dcur, p2c, adj_all);
    cudaEventRecord(evCSR, sC);

    // ---- stream A (0): patient embedding ----
    k_embed_pat<<<2048, 128>>>(x_pat, Wp, bp, hp[0], hp16);
    cudaEventRecord(evE, 0);

    // ---- stream B: lab/dis embeddings + layer-0 lab/dis pipeline ----
    k_embed_lab<<<(int)((SZ_HL + 255) / 256), 256, 0, sB>>>(x_lab, Wlab, blab, hl[0]);
    k_embed_dis<<<(int)((SZ_HD + 255) / 256), 256, 0, sB>>>(x_dis, Wdis, bdis, hd[0]);
    k_gemm<<<444, 128, 65536, sB>>>(hl[0], Wl[0] + 2 * HH, nullptr, tl, tl16, NLAB, 0);
    k_gemm<<<63, 128, 65536, sB>>>(hd[0], Wl[0] + 3 * HH, nullptr, td, td16, NDIS, 0);
    cudaEventRecord(evTD0, sB);
    cudaStreamWaitEvent(sB, evE, 0);
    cudaStreamWaitEvent(sB, evCSR, 0);
    k_gather_mean<<<(NLAB * 32 + 255) / 256, 256, 0, sB>>>(loff, adj_all, hp16, la, NLAB);
    k_gather_mean_w8<<<(NDIS * 8 * 32 + 255) / 256, 256, 0, sB>>>(doff, adj_all, hp16, da[0], NDIS);
    cudaEventRecord(evG0, sB);
    k_gemm<<<444, 128, 65536, sB>>>(la, Wl[0], bl[0], hl[1], nullptr, NLAB, 0);
    k_gemm<<<444, 128, 65536, sB>>>(hl[0], Wr[0], nullptr, hl[1], nullptr, NLAB, GF_ACC);
    k_stats<<<1024, 128, 0, sB>>>(hl[1], NLAB, sm + 1 * H, sq + 1 * H);
    k_bn<<<2048, 256, 0, sB>>>(hl[1], nullptr, SZ_HL, 1.f / NLAB, sm + 1 * H, sq + 1 * H,
                               bng[0] + 1 * H, bnb[0] + 1 * H);
    k_gemm<<<63, 128, 65536, sB>>>(da[0], Wl[0] + HH, bl[0] + H, hd[1], nullptr, NDIS, 0);
    k_gemm<<<63, 128, 65536, sB>>>(hd[0], Wr[0] + HH, nullptr, hd[1], nullptr, NDIS, GF_ACC);
    k_stats<<<500, 128, 0, sB>>>(hd[1], NDIS, sm + 2 * H, sq + 2 * H);
    k_bn<<<256, 256, 0, sB>>>(hd[1], nullptr, SZ_HD, 1.f / NDIS, sm + 2 * H, sq + 2 * H,
                              bng[0] + 2 * H, bnb[0] + 2 * H);

    // ---- stream A: layer-0 patient pipeline (tensor-core GEMM) ----
    k_addw16<<<(HH + 255) / 256, 256>>>(Wr[0] + 2 * HH, Wr[0] + 3 * HH, wt16);
    k_mma<<<444, 128, MMA_SMEM>>>(hp16, wt16, hp[1], NPAT);
    cudaStreamWaitEvent(0, evCSR, 0);
    cudaStreamWaitEvent(0, evTD0, 0);
    k_gather_pat<<<NPAT / 8, 256>>>(p1o, adj_all, tl16, p2o, adj_all, td16,
                                    bl[0] + 2 * H, bl[0] + 3 * H, hp[1],
                                    sm + 0 * H, sq + 0 * H);
    cudaEventRecord(evGP0, 0);   // tl16/td16 free for reuse
    cudaStreamWaitEvent(0, evG0, 0);   // hp16 (layer-0) fully consumed
    k_bn<<<8192, 256>>>(hp[1], hp16, SZ_HP, 1.f / NPAT, sm + 0 * H, sq + 0 * H,
                        bng[0] + 0 * H, bnb[0] + 0 * H);
    cudaEventRecord(evHP0, 0);   // hp16 v2 ready

    // ---- stream B: layer-1 lab/dis pipeline ----
    cudaStreamWaitEvent(sB, evGP0, 0);
    k_gemm<<<444, 128, 65536, sB>>>(hl[1], Wl[1] + 2 * HH, nullptr, tl, tl16, NLAB, 0);
    k_gemm<<<63, 128, 65536, sB>>>(hd[1], Wl[1] + 3 * HH, nullptr, td, td16, NDIS, 0);
    cudaEventRecord(evTD1, sB);
    cudaStreamWaitEvent(sB, evHP0, 0);
    k_gather_mean<<<(NLAB * 32 + 255) / 256, 256, 0, sB>>>(loff, adj_all, hp16, la, NLAB);
    k_gather_mean_w8<<<(NDIS * 8 * 32 + 255) / 256, 256, 0, sB>>>(doff, adj_all, hp16, da[1], NDIS);
    cudaEventRecord(evG1, sB);
    k_gemm<<<444, 128, 65536, sB>>>(la, Wl[1], bl[1], hl[0], nullptr, NLAB, 0);
    k_gemm<<<444, 128, 65536, sB>>>(hl[1], Wr[1], nullptr, hl[0], nullptr, NLAB, GF_ACC);
    k_stats<<<1024, 128, 0, sB>>>(hl[0], NLAB, sm + 4 * H, sq + 4 * H);
    k_bn<<<2048, 256, 0, sB>>>(hl[0], nullptr, SZ_HL, 1.f / NLAB, sm + 4 * H, sq + 4 * H,
                               bng[1] + 1 * H, bnb[1] + 1 * H);
    k_gemm<<<63, 128, 65536, sB>>>(da[1], Wl[1] + HH, bl[1] + H, hd[0], nullptr, NDIS, 0);
    k_gemm<<<63, 128, 65536, sB>>>(hd[1], Wr[1] + HH, nullptr, hd[0], nullptr, NDIS, GF_ACC);
    k_stats<<<500, 128, 0, sB>>>(hd[0], NDIS, sm + 5 * H, sq + 5 * H);
    k_bn<<<256, 256, 0, sB>>>(hd[0], nullptr, SZ_HD, 1.f / NDIS, sm + 5 * H, sq + 5 * H,
                              bng[1] + 2 * H, bnb[1] + 2 * H);
    cudaEventRecord(evBfin, sB);

    // ---- stream A: layer-1 patient pipeline + head ----
    k_addw16<<<(HH + 255) / 256, 256>>>(Wr[1] + 2 * HH, Wr[1] + 3 * HH, wt16);
    k_mma<<<444, 128, MMA_SMEM>>>(hp16, wt16, hp[0], NPAT);
    cudaStreamWaitEvent(0, evTD1, 0);
    k_gather_pat<<<NPAT / 8, 256>>>(p1o, adj_all, tl16, p2o, adj_all, td16,
                                    bl[1] + 2 * H, bl[1] + 3 * H, hp[0],
                                    sm + 3 * H, sq + 3 * H);
    k_bn<<<8192, 256>>>(hp[0], nullptr, SZ_HP, 1.f / NPAT, sm + 3 * H, sq + 3 * H,
                        bng[1] + 0 * H, bnb[1] + 0 * H);
    k_gemm<<<888, 64, 32768>>>(hp[0], fc1W, fc1b, t1, nullptr, NPAT, GF_RELU);
    k_head<<<(NPAT + 3) / 4, 128>>>(t1, fc2W, fc2b, (float*)d_out);

    cudaStreamWaitEvent(0, evBfin, 0);
}

// round 17
// speedup vs baseline: 1.1931x; 1.0650x over previous
#include <cuda_runtime.h>
#include <cuda_fp16.h>
#include <math.h>

#define NPAT 100000
#define NLAB 10000
#define NDIS 500
#define NE1  2000000
#define NE2  500000
#define H    128
#define HH   (128*128)
#define FC1C 64
#define NOUT 10
#define EPSBN 1e-5f

#define NTOTI (NLAB + NDIS + NPAT + NPAT)
#define STILE 1024
#define SNB   ((NTOTI + STILE - 1) / STILE)

// ---------------- scratch layout (float slots) ----------------
constexpr long SZ_HP = (long)NPAT * H;
constexpr long SZ_HL = (long)NLAB * H;
constexpr long SZ_HD = (long)NDIS * H;

constexpr long O_HP0 = 0;
constexpr long O_HP1 = O_HP0 + SZ_HP;
constexpr long O_HL0 = O_HP1 + SZ_HP;
constexpr long O_HL1 = O_HL0 + SZ_HL;
constexpr long O_HD0 = O_HL1 + SZ_HL;
constexpr long O_HD1 = O_HD0 + SZ_HD;
constexpr long O_TL  = O_HD1 + SZ_HD;          // fp32 scratch for tl GEMM out
constexpr long O_TD  = O_TL + SZ_HL;
constexpr long O_WT  = O_TD + SZ_HD;           // wt16a | wt16b (each HH halves)
constexpr long O_FW16 = O_WT + HH;             // fc1W fp16 (8192 halves = 4096 slots)
constexpr long O_T1  = O_FW16 + 4096;
constexpr long O_LA  = O_T1 + (long)NPAT * FC1C;
constexpr long O_HP16  = O_LA + SZ_HL;
constexpr long O_HP16B = O_HP16 + SZ_HP / 2;
constexpr long O_TL16A = O_HP16B + SZ_HP / 2;
constexpr long O_TL16B = O_TL16A + SZ_HL / 2;
constexpr long O_TD16A = O_TL16B + SZ_HL / 2;
constexpr long O_TD16B = O_TD16A + SZ_HD / 2;
// --- zero-once region: da0 | da1 | sm[6H] | sq[6H] | counts[NTOTI] ---
constexpr long O_DA0 = O_TD16B + SZ_HD / 2;
constexpr long O_DA1 = O_DA0 + SZ_HD;
constexpr long O_SM  = O_DA1 + SZ_HD;
constexpr long O_SQ  = O_SM + 6 * H;
constexpr long O_CL  = O_SQ + 6 * H;
constexpr long O_OFF = O_CL + NTOTI;
constexpr long O_CUR = O_OFF + NTOTI + 4;
constexpr long O_PART= O_CUR + NTOTI;
constexpr long O_ADJ = O_PART + 512;
constexpr long O_END = O_ADJ + 2L * (NE1 + NE2);

constexpr long Z_N4  = (O_OFF - O_DA0) / 4;
constexpr long TOT4  = (O_END + 3) / 4;

__device__ float4 g_buf[TOT4];

// ---------------- utility kernels ----------------

__global__ void k_zero4(float4* p, long n4) {
    long i  = (long)blockIdx.x * blockDim.x + threadIdx.x;
    long st = (long)gridDim.x * blockDim.x;
    float4 z = make_float4(0.f, 0.f, 0.f, 0.f);
    for (; i < n4; i += st) p[i] = z;
}

__global__ void k_cvt16(const float* __restrict__ src, __half* __restrict__ dst, int n) {
    int i = blockIdx.x * blockDim.x + threadIdx.x;
    if (i < n) dst[i] = __float2half_rn(src[i]);
}

__global__ void k_count(const int* __restrict__ src, const int* __restrict__ dst, int n,
                        int* cs, int* cd) {
    int i  = blockIdx.x * blockDim.x + threadIdx.x;
    int st = gridDim.x * blockDim.x;
    for (; i < n; i += st) {
        atomicAdd(cs + src[i], 1);
        atomicAdd(cd + dst[i], 1);
    }
}

__global__ void k_psum(const int* __restrict__ cnt, int* __restrict__ part) {
    __shared__ int wsum[8];
    int t = threadIdx.x;
    long base = (long)blockIdx.x * STILE + t * 4;
    int s = 0;
#pragma unroll
    for (int u = 0; u < 4; u++) {
        long i = base + u;
        if (i < NTOTI) s += cnt[i];
    }
#pragma unroll
    for (int o = 16; o > 0; o >>= 1) s += __shfl_xor_sync(0xffffffffu, s, o);
    if ((t & 31) == 0) wsum[t >> 5] = s;
    __syncthreads();
    if (t == 0) {
        int tot = 0;
#pragma unroll
        for (int i = 0; i < 8; i++) tot += wsum[i];
        part[blockIdx.x] = tot;
    }
}

__global__ void k_scanpart(int* __restrict__ part, int* __restrict__ off_end) {
    __shared__ int sh[256];
    int t = threadIdx.x;
    int v = (t < SNB) ? part[t] : 0;
    sh[t] = v;
    __syncthreads();
#pragma unroll
    for (int d = 1; d < 256; d <<= 1) {
        int x = (t >= d) ? sh[t - d] : 0;
        __syncthreads();
        sh[t] += x;
        __syncthreads();
    }
    if (t < SNB) part[t] = sh[t] - v;
    if (t == 255) *off_end = sh[255];
}

__global__ void k_scanfinal(const int* __restrict__ cnt, const int* __restrict__ part,
                            int* __restrict__ off, int* __restrict__ cur) {
    __shared__ int wpre[8];
    int t = threadIdx.x, lane = t & 31, w = t >> 5;
    long base = (long)blockIdx.x * STILE + t * 4;
    int v[4];
    int s = 0;
#pragma unroll
    for (int u = 0; u < 4; u++) {
        v[u] = (base + u < NTOTI) ? cnt[base + u] : 0;
        s += v[u];
    }
    int incl = s;
#pragma unroll
    for (int o = 1; o < 32; o <<= 1) {
        int x = __shfl_up_sync(0xffffffffu, incl, o);
        if (lane >= o) incl += x;
    }
    int excl = incl - s;
    if (lane == 31) wpre[w] = incl;
    __syncthreads();
    if (t == 0) {
        int run = 0;
#pragma unroll
        for (int i = 0; i < 8; i++) { int x = wpre[i]; wpre[i] = run; run += x; }
    }
    __syncthreads();
    int pre = part[blockIdx.x] + wpre[w] + excl;
#pragma unroll
    for (int u = 0; u < 4; u++) {
        if (base + u < NTOTI) { off[base + u] = pre; cur[base + u] = pre; }
        pre += v[u];
    }
}

__global__ void k_fill(const int* __restrict__ src, const int* __restrict__ dst, int n,
                       int* curd, int* curs, int* __restrict__ adj) {
    int i  = blockIdx.x * blockDim.x + threadIdx.x;
    int st = gridDim.x * blockDim.x;
    for (; i < n; i += st) {
        int s = src[i], d = dst[i];
        adj[atomicAdd(curd + d, 1)] = s;
        adj[atomicAdd(curs + s, 1)] = d;
    }
}

// ---------------- embeddings ----------------

__global__ void k_embed_pat(const float* __restrict__ x, const float* __restrict__ Wp,
                            const float* __restrict__ bp, __half* __restrict__ out16) {
    __shared__ float Wsh[16 * H];
    __shared__ float xsh[8][16];
    int tid = threadIdx.x;
    for (int i = tid; i < 16 * H; i += 128) Wsh[i] = Wp[i];
    __syncthreads();
    float wreg[16];
#pragma unroll
    for (int k = 0; k < 16; k++) wreg[k] = Wsh[k * H + tid];
    float bb = bp[tid];
    for (long base = (long)blockIdx.x * 8; base < NPAT; base += (long)gridDim.x * 8) {
        int nr = (int)((NPAT - base) < 8 ? (NPAT - base) : 8);
        if (tid < nr * 16) xsh[tid >> 4][tid & 15] = x[base * 16 + tid];
        __syncthreads();
        for (int r = 0; r < nr; r++) {
            float acc = bb;
#pragma unroll
            for (int k = 0; k < 16; k++) acc = fmaf(xsh[r][k], wreg[k], acc);
            out16[(base + r) * H + tid] = __float2half_rn(acc);
        }
        __syncthreads();
    }
}

__global__ void k_embed_lab(const float* __restrict__ x, const float* __restrict__ W,
                            const float* __restrict__ b, float* __restrict__ out) {
    long idx = (long)blockIdx.x * blockDim.x + threadIdx.x;
    if (idx >= (long)NLAB * H) return;
    int i = (int)(idx >> 7), h = (int)(idx & 127);
    out[idx] = x[i] * W[h] + b[h];
}

__global__ void k_embed_dis(const float* __restrict__ x, const float* __restrict__ W,
                            const float* __restrict__ b, float* __restrict__ out) {
    long idx = (long)blockIdx.x * blockDim.x + threadIdx.x;
    if (idx >= (long)NDIS * H) return;
    int i = (int)(idx >> 7), h = (int)(idx & 127);
    out[idx] = x[2 * i] * W[h] + x[2 * i + 1] * W[H + h] + b[h];
}

// ---------------- gather aggregation (fp16 sources, fp32 accumulate) --------

__device__ __forceinline__ void red4(float* p, float4 v) {
    asm volatile("red.global.add.v4.f32 [%0], {%1,%2,%3,%4};"
                 :: "l"(p), "f"(v.x), "f"(v.y), "f"(v.z), "f"(v.w) : "memory");
}

__device__ __forceinline__ void acc8(float4& acc, uint2 u) {
    __half2 h0 = *(__half2*)&u.x;
    __half2 h1 = *(__half2*)&u.y;
    float2 f0 = __half22float2(h0);
    float2 f1 = __half22float2(h1);
    acc.x += f0.x; acc.y += f0.y; acc.z += f1.x; acc.w += f1.y;
}

__device__ __forceinline__ float4 gmean16(const int* __restrict__ off,
                                          const int* __restrict__ adj,
                                          const __half* __restrict__ src,
                                          int row, int lane) {
    int s = off[row], e = off[row + 1];
    float4 acc = make_float4(0.f, 0.f, 0.f, 0.f);
    int j = s;
    for (; j + 4 <= e; j += 4) {
        int i0 = __ldg(adj + j),     i1 = __ldg(adj + j + 1);
        int i2 = __ldg(adj + j + 2), i3 = __ldg(adj + j + 3);
        uint2 u0 = __ldg((const uint2*)(src + (size_t)i0 * H) + lane);
        uint2 u1 = __ldg((const uint2*)(src + (size_t)i1 * H) + lane);
        uint2 u2 = __ldg((const uint2*)(src + (size_t)i2 * H) + lane);
        uint2 u3 = __ldg((const uint2*)(src + (size_t)i3 * H) + lane);
        acc8(acc, u0); acc8(acc, u1); acc8(acc, u2); acc8(acc, u3);
    }
    for (; j < e; j++) {
        int i0 = __ldg(adj + j);
        uint2 u = __ldg((const uint2*)(src + (size_t)i0 * H) + lane);
        acc8(acc, u);
    }
    float r = 1.f / fmaxf((float)(e - s), 1.f);
    acc.x *= r; acc.y *= r; acc.z *= r; acc.w *= r;
    return acc;
}

__global__ void k_gather_mean(const int* __restrict__ off, const int* __restrict__ adj,
                              const __half* __restrict__ src, float* __restrict__ out,
                              int Nd) {
    int w    = (blockIdx.x * blockDim.x + threadIdx.x) >> 5;
    int lane = threadIdx.x & 31;
    if (w >= Nd) return;
    float4 m = gmean16(off, adj, src, w, lane);
    ((float4*)(out + (size_t)w * H))[lane] = m;
}

__global__ void k_gather_mean_w8(const int* __restrict__ off, const int* __restrict__ adj,
                                 const __half* __restrict__ src, float* __restrict__ out,
                                 int Nd) {
    int gw   = (blockIdx.x * blockDim.x + threadIdx.x) >> 5;
    int lane = threadIdx.x & 31;
    int row  = gw >> 3, sub = gw & 7;
    if (row >= Nd) return;
    int s = off[row], e = off[row + 1];
    float4 acc = make_float4(0.f, 0.f, 0.f, 0.f);
    int j = s + sub * 4;
    for (; j + 4 <= e; j += 32) {
        int i0 = __ldg(adj + j),     i1 = __ldg(adj + j + 1);
        int i2 = __ldg(adj + j + 2), i3 = __ldg(adj + j + 3);
        uint2 u0 = __ldg((const uint2*)(src + (size_t)i0 * H) + lane);
        uint2 u1 = __ldg((const uint2*)(src + (size_t)i1 * H) + lane);
        uint2 u2 = __ldg((const uint2*)(src + (size_t)i2 * H) + lane);
        uint2 u3 = __ldg((const uint2*)(src + (size_t)i3 * H) + lane);
        acc8(acc, u0); acc8(acc, u1); acc8(acc, u2); acc8(acc, u3);
    }
    if (j < e) {
        for (int t = j; t < e; t++) {
            int i0 = __ldg(adj + t);
            uint2 u = __ldg((const uint2*)(src + (size_t)i0 * H) + lane);
            acc8(acc, u);
        }
    }
    float r = 1.f / fmaxf((float)(e - s), 1.f);
    acc.x *= r; acc.y *= r; acc.z *= r; acc.w *= r;
    red4((float*)((float4*)(out + (size_t)row * H) + lane), acc);
}

// patients: out += means + biases, fused BN column stats
__global__ void k_gather_pat(const int* __restrict__ off1, const int* __restrict__ adj1,
                             const __half* __restrict__ srcL,
                             const int* __restrict__ off2, const int* __restrict__ adj2,
                             const __half* __restrict__ srcD,
                             const float* __restrict__ b2, const float* __restrict__ b3,
                             float* __restrict__ out,
                             float* __restrict__ gsum, float* __restrict__ gsq) {
    __shared__ float bsum[H], bsq[H];
    int tid  = threadIdx.x;
    if (tid < H) { bsum[tid] = 0.f; bsq[tid] = 0.f; }
    __syncthreads();
    int w    = (blockIdx.x * blockDim.x + tid) >> 5;
    int lane = tid & 31;
    float4 a1 = gmean16(off1, adj1, srcL, w, lane);
    float4 a2 = gmean16(off2, adj2, srcD, w, lane);
    float4 bb2 = ((const float4*)b2)[lane];
    float4 bb3 = ((const float4*)b3)[lane];
    float4* o = (float4*)(out + (size_t)w * H) + lane;
    float4 v = *o;
    v.x += a1.x + a2.x + bb2.x + bb3.x;
    v.y += a1.y + a2.y + bb2.y + bb3.y;
    v.z += a1.z + a2.z + bb2.z + bb3.z;
    v.w += a1.w + a2.w + bb2.w + bb3.w;
    *o = v;
    int c = lane * 4;
    atomicAdd(bsum + c + 0, v.x); atomicAdd(bsq + c + 0, v.x * v.x);
    atomicAdd(bsum + c + 1, v.y); atomicAdd(bsq + c + 1, v.y * v.y);
    atomicAdd(bsum + c + 2, v.z); atomicAdd(bsq + c + 2, v.z * v.z);
    atomicAdd(bsum + c + 3, v.w); atomicAdd(bsq + c + 3, v.w * v.w);
    __syncthreads();
    if (tid < H) {
        atomicAdd(gsum + tid, bsum[tid]);
        atomicAdd(gsq + tid, bsq[tid]);
    }
}

// ---------------- fp16 tensor-core GEMM: out[N,128] = A16 @ W16[128,128] ----
#define MMA_SMEM (128 * 272 + 64 * 272)
__global__ void __launch_bounds__(128) k_mma(const __half* __restrict__ A16,
                                             const __half* __restrict__ W16,
                                             float* __restrict__ out, int N) {
    extern __shared__ char smem[];
    __half* Wsh = (__half*)smem;
    __half* Ash = (__half*)(smem + 128 * 272);
    unsigned Wbase = (unsigned)__cvta_generic_to_shared(Wsh);
    unsigned Abase = (unsigned)__cvta_generic_to_shared(Ash);
    int tid = threadIdx.x, lane = tid & 31, w = tid >> 5;

    {
        const unsigned* src = (const unsigned*)W16;
        unsigned* dst = (unsigned*)Wsh;
        for (int i = tid; i < 8192; i += 128) {
            int r = i >> 6, c = i & 63;
            dst[r * 68 + c] = src[i];
        }
    }

    int arow  = w * 16 + (lane & 7) + ((lane >> 3) & 1) * 8;
    int acolb = ((lane >> 4) & 1) * 16;
    int brow  = lane & 15;

    int ntiles = (N + 63) >> 6;
    for (int t = blockIdx.x; t < ntiles; t += gridDim.x) {
        long base = (long)t * 64;
        __syncthreads();
        {
            const uint2* srcA = (const uint2*)A16;
            uint2* dstA = (uint2*)Ash;
            for (int i = tid; i < 2048; i += 128) {
                int r = i >> 5, c = i & 31;
                long gr = base + r;
                uint2 vv = (gr < N) ? srcA[gr * 32 + c] : make_uint2(0u, 0u);
                dstA[r * 34 + c] = vv;
            }
        }
        __syncthreads();

        float d[16][4];
#pragma unroll
        for (int nt = 0; nt < 16; nt++) {
            d[nt][0] = 0.f; d[nt][1] = 0.f; d[nt][2] = 0.f; d[nt][3] = 0.f;
        }

#pragma unroll
        for (int ks = 0; ks < 8; ks++) {
            unsigned a0, a1, a2, a3;
            unsigned aaddr = Abase + arow * 272 + ks * 32 + acolb;
            asm volatile("ldmatrix.sync.aligned.m8n8.x4.shared.b16 {%0,%1,%2,%3}, [%4];"
                         : "=r"(a0), "=r"(a1), "=r"(a2), "=r"(a3) : "r"(aaddr));
            unsigned baddr0 = Wbase + (ks * 16 + brow) * 272;
#pragma unroll
            for (int nt = 0; nt < 16; nt++) {
                unsigned b0, b1;
                asm volatile("ldmatrix.sync.aligned.m8n8.x2.trans.shared.b16 {%0,%1}, [%2];"
                             : "=r"(b0), "=r"(b1) : "r"(baddr0 + nt * 16));
                asm volatile("mma.sync.aligned.m16n8k16.row.col.f32.f16.f16.f32 "
                             "{%0,%1,%2,%3}, {%4,%5,%6,%7}, {%8,%9}, {%0,%1,%2,%3};"
                             : "+f"(d[nt][0]), "+f"(d[nt][1]), "+f"(d[nt][2]), "+f"(d[nt][3])
                             : "r"(a0), "r"(a1), "r"(a2), "r"(a3), "r"(b0), "r"(b1));
            }
        }

        int g = lane >> 2, t2 = (lane & 3) * 2;
        long r0 = base + w * 16 + g;
        long r1 = r0 + 8;
#pragma unroll
        for (int nt = 0; nt < 16; nt++) {
            int col = nt * 8 + t2;
            if (r0 < N) *(float2*)&out[r0 * H + col] = make_float2(d[nt][0], d[nt][1]);
            if (r1 < N) *(float2*)&out[r1 * H + col] = make_float2(d[nt][2], d[nt][3]);
        }
    }
}

// ---------------- fc1 tensor-core GEMM: t1[N,64] = relu(A16 @ W16[128,64] + b) ----
#define MMA1_SMEM (128 * 272 + 64 * 272 + 256)
__global__ void __launch_bounds__(128) k_mma_fc1(const __half* __restrict__ A16,
                                                 const __half* __restrict__ W16,
                                                 const float* __restrict__ bias,
                                                 float* __restrict__ out, int N) {
    extern __shared__ char smem[];
    __half* Wsh = (__half*)smem;
    __half* Ash = (__half*)(smem + 128 * 272);
    float*  bsh = (float*)(smem + 128 * 272 + 64 * 272);
    unsigned Wbase = (unsigned)__cvta_generic_to_shared(Wsh);
    unsigned Abase = (unsigned)__cvta_generic_to_shared(Ash);
    int tid = threadIdx.x, lane = tid & 31, w = tid >> 5;

    {
        const unsigned* src = (const unsigned*)W16;   // 128 rows x 32 words
        unsigned* dst = (unsigned*)Wsh;
        for (int i = tid; i < 4096; i += 128) {
            int r = i >> 5, c = i & 31;
            dst[r * 68 + c] = src[i];
        }
        if (tid < 64) bsh[tid] = bias[tid];
    }

    int arow  = w * 16 + (lane & 7) + ((lane >> 3) & 1) * 8;
    int acolb = ((lane >> 4) & 1) * 16;
    int brow  = lane & 15;

    int ntiles = (N + 63) >> 6;
    for (int t = blockIdx.x; t < ntiles; t += gridDim.x) {
        long base = (long)t * 64;
        __syncthreads();
        {
            const uint2* srcA = (const uint2*)A16;
            uint2* dstA = (uint2*)Ash;
            for (int i = tid; i < 2048; i += 128) {
                int r = i >> 5, c = i & 31;
                long gr = base + r;
                uint2 vv = (gr < N) ? srcA[gr * 32 + c] : make_uint2(0u, 0u);
                dstA[r * 34 + c] = vv;
            }
        }
        __syncthreads();

        float d[8][4];
#pragma unroll
        for (int nt = 0; nt < 8; nt++) {
            d[nt][0] = 0.f; d[nt][1] = 0.f; d[nt][2] = 0.f; d[nt][3] = 0.f;
        }

#pragma unroll
        for (int ks = 0; ks < 8; ks++) {
            unsigned a0, a1, a2, a3;
            unsigned aaddr = Abase + arow * 272 + ks * 32 + acolb;
            asm volatile("ldmatrix.sync.aligned.m8n8.x4.shared.b16 {%0,%1,%2,%3}, [%4];"
                         : "=r"(a0), "=r"(a1), "=r"(a2), "=r"(a3) : "r"(aaddr));
            unsigned baddr0 = Wbase + (ks * 16 + brow) * 272;
#pragma unroll
            for (int nt = 0; nt < 8; nt++) {
                unsigned b0, b1;
                asm volatile("ldmatrix.sync.aligned.m8n8.x2.trans.shared.b16 {%0,%1}, [%2];"
                             : "=r"(b0), "=r"(b1) : "r"(baddr0 + nt * 16));
                asm volatile("mma.sync.aligned.m16n8k16.row.col.f32.f16.f16.f32 "
                             "{%0,%1,%2,%3}, {%4,%5,%6,%7}, {%8,%9}, {%0,%1,%2,%3};"
                             : "+f"(d[nt][0]), "+f"(d[nt][1]), "+f"(d[nt][2]), "+f"(d[nt][3])
                             : "r"(a0), "r"(a1), "r"(a2), "r"(a3), "r"(b0), "r"(b1));
            }
        }

        int g = lane >> 2, t2 = (lane & 3) * 2;
        long r0 = base + w * 16 + g;
        long r1 = r0 + 8;
#pragma unroll
        for (int nt = 0; nt < 8; nt++) {
            int col = nt * 8 + t2;
            float bx = bsh[col], by = bsh[col + 1];
            if (r0 < N) *(float2*)&out[r0 * FC1C + col] =
                make_float2(fmaxf(d[nt][0] + bx, 0.f), fmaxf(d[nt][1] + by, 0.f));
            if (r1 < N) *(float2*)&out[r1 * FC1C + col] =
                make_float2(fmaxf(d[nt][2] + bx, 0.f), fmaxf(d[nt][3] + by, 0.f));
        }
    }
}

// ---------------- fp32 GEMM (labs/diseases) ----------------
#define GF_ACC 1
#define GF_RELU 2
__global__ void __launch_bounds__(128) k_gemm(const float* __restrict__ A,
                                              const float* __restrict__ W,
                                              const float* __restrict__ bias,
                                              float* __restrict__ out,
                                              __half* __restrict__ out16,
                                              int N, int flags) {
    extern __shared__ float Wsh[];
    __shared__ float4 ashA[H];
    __shared__ float4 ashB[H];
    int NC  = blockDim.x;
    int tid = threadIdx.x;
    for (int i = tid; i < H * NC; i += NC) Wsh[i] = W[i];
    __syncthreads();
    float bb = bias ? bias[tid] : 0.f;
    for (long base = (long)blockIdx.x * 8; base < N; base += (long)gridDim.x * 8) {
        int nr = (int)(((long)N - base) < 8 ? ((long)N - base) : 8);
        for (int k = tid; k < H; k += NC) {
            const float* Ak = A + base * H + k;
            float4 va, vb;
            va.x = Ak[0];
            va.y = nr > 1 ? Ak[1 * H] : 0.f;
            va.z = nr > 2 ? Ak[2 * H] : 0.f;
            va.w = nr > 3 ? Ak[3 * H] : 0.f;
            vb.x = nr > 4 ? Ak[4 * H] : 0.f;
            vb.y = nr > 5 ? Ak[5 * H] : 0.f;
            vb.z = nr > 6 ? Ak[6 * H] : 0.f;
            vb.w = nr > 7 ? Ak[7 * H] : 0.f;
            ashA[k] = va;
            ashB[k] = vb;
        }
        __syncthreads();
        float a0 = bb, a1 = bb, a2 = bb, a3 = bb;
        float a4 = bb, a5 = bb, a6 = bb, a7 = bb;
#pragma unroll 16
        for (int k = 0; k < H; k++) {
            float4 av = ashA[k];
            float4 bv = ashB[k];
            float wv  = Wsh[k * NC + tid];
            a0 = fmaf(av.x, wv, a0);
            a1 = fmaf(av.y, wv, a1);
            a2 = fmaf(av.z, wv, a2);
            a3 = fmaf(av.w, wv, a3);
            a4 = fmaf(bv.x, wv, a4);
            a5 = fmaf(bv.y, wv, a5);
            a6 = fmaf(bv.z, wv, a6);
            a7 = fmaf(bv.w, wv, a7);
        }
        float rr[8] = {a0, a1, a2, a3, a4, a5, a6, a7};
        for (int r = 0; r < nr; r++) {
            long o  = (base + r) * NC + tid;
            float v = rr[r];
            if (flags & GF_ACC)  v += out[o];
            if (flags & GF_RELU) v = fmaxf(v, 0.f);
            out[o] = v;
            if (out16) out16[o] = __float2half_rn(v);
        }
        __syncthreads();
    }
}

__global__ void k_addw16(const float* __restrict__ A, const float* __restrict__ Bm,
                         __half* __restrict__ out) {
    int idx = blockIdx.x * blockDim.x + threadIdx.x;
    if (idx < HH) out[idx] = __float2half_rn(A[idx] + Bm[idx]);
}

// ---------------- BatchNorm ----------------
__global__ void k_stats(const float* __restrict__ X, int N,
                        float* __restrict__ sum, float* __restrict__ sumsq) {
    int tid = threadIdx.x;
    float s = 0.f, ss = 0.f;
    for (long r = blockIdx.x; r < N; r += gridDim.x) {
        float v = X[r * H + tid];
        s += v;
        ss = fmaf(v, v, ss);
    }
    atomicAdd(sum + tid, s);
    atomicAdd(sumsq + tid, ss);
}

__global__ void k_bn(float* __restrict__ X, __half* __restrict__ X16, long n, float invN,
                     const float* __restrict__ sum, const float* __restrict__ sumsq,
                     const float* __restrict__ g, const float* __restrict__ b, int wf32) {
    long idx = (long)blockIdx.x * blockDim.x + threadIdx.x;
    long st  = (long)gridDim.x * blockDim.x;
    for (; idx < n; idx += st) {
        int h   = (int)(idx & 127);
        float m = sum[h] * invN;
        float var = sumsq[h] * invN - m * m;
        float v = (X[idx] - m) * rsqrtf(var + EPSBN) * g[h] + b[h];
        v = fmaxf(v, 0.f);
        if (wf32) X[idx] = v;
        if (X16) X16[idx] = __float2half_rn(v);
    }
}

// ---------------- head ----------------
__global__ void k_head(const float* __restrict__ T, const float* __restrict__ W2,
                       const float* __restrict__ b2, float* __restrict__ out) {
    __shared__ float tsh[4][64];
    int w    = threadIdx.x >> 5;
    int lane = threadIdx.x & 31;
    long row = (long)blockIdx.x * 4 + w;
    if (row >= NPAT) return;
    tsh[w][lane]      = T[row * 64 + lane];
    tsh[w][lane + 32] = T[row * 64 + 32 + lane];
    __syncwarp();
    float z;
    if (lane < NOUT) {
        z = b2[lane];
#pragma unroll 8
        for (int j = 0; j < 64; j++) z = fmaf(tsh[w][j], __ldg(W2 + j * NOUT + lane), z);
    } else {
        z = -INFINITY;
    }
    float m = z;
#pragma unroll
    for (int off = 16; off > 0; off >>= 1) m = fmaxf(m, __shfl_xor_sync(0xffffffffu, m, off));
    float e = (lane < NOUT) ? __expf(z - m) : 0.f;
    float ssum = e;
#pragma unroll
    for (int off = 16; off > 0; off >>= 1) ssum += __shfl_xor_sync(0xffffffffu, ssum, off);
    float lse = m + __logf(ssum);
    if (lane < NOUT) out[row * NOUT + lane] = z - lse;
}

// ---------------- host ----------------
extern "C" void kernel_launch(void* const* d_in, const int* in_sizes, int n_in,
                              void* d_out, int out_size) {
    const float* x_pat = (const float*)d_in[0];
    const float* x_lab = (const float*)d_in[1];
    const float* x_dis = (const float*)d_in[2];
    const float* Wp    = (const float*)d_in[3];
    const float* bp    = (const float*)d_in[4];
    const float* Wlab  = (const float*)d_in[5];
    const float* blab  = (const float*)d_in[6];
    const float* Wdis  = (const float*)d_in[7];
    const float* bdis  = (const float*)d_in[8];
    const float* Wl[2] = {(const float*)d_in[9],  (const float*)d_in[12]};
    const float* bl[2] = {(const float*)d_in[10], (const float*)d_in[13]};
    const float* Wr[2] = {(const float*)d_in[11], (const float*)d_in[14]};
    const float* bng[2] = {(const float*)d_in[15], (const float*)d_in[17]};
    const float* bnb[2] = {(const float*)d_in[16], (const float*)d_in[18]};
    const float* fc1W  = (const float*)d_in[19];
    const float* fc1b  = (const float*)d_in[20];
    const float* fc2W  = (const float*)d_in[21];
    const float* fc2b  = (const float*)d_in[22];
    const int* s1 = (const int*)d_in[23];
    const int* d1 = (const int*)d_in[24];
    const int* s2 = (const int*)d_in[25];
    const int* d2 = (const int*)d_in[26];

    float* B = nullptr;
    cudaGetSymbolAddress((void**)&B, g_buf);

    float* hp[2] = {B + O_HP0, B + O_HP1};
    float* hl[2] = {B + O_HL0, B + O_HL1};
    float* hd[2] = {B + O_HD0, B + O_HD1};
    float* tl = B + O_TL;
    float* td = B + O_TD;
    __half* wt16a = (__half*)(B + O_WT);
    __half* wt16b = (__half*)(B + O_WT) + HH;
    __half* fw16  = (__half*)(B + O_FW16);
    float* t1 = B + O_T1;
    float* la = B + O_LA;
    __half* hp16  = (__half*)(B + O_HP16);
    __half* hp16b = (__half*)(B + O_HP16B);
    __half* tl16[2] = {(__half*)(B + O_TL16A), (__half*)(B + O_TL16B)};
    __half* td16[2] = {(__half*)(B + O_TD16A), (__half*)(B + O_TD16B)};
    float* da[2] = {B + O_DA0, B + O_DA1};
    float* sm = B + O_SM;
    float* sq = B + O_SQ;
    int* cnt_all = (int*)(B + O_CL);
    int* off_all = (int*)(B + O_OFF);
    int* cur_all = (int*)(B + O_CUR);
    int* part    = (int*)(B + O_PART);
    int* adj_all = (int*)(B + O_ADJ);

    int* cl  = cnt_all;
    int* cd  = cnt_all + NLAB;
    int* cp1 = cnt_all + NLAB + NDIS;
    int* cp2 = cnt_all + NLAB + NDIS + NPAT;
    int* loff = off_all;
    int* doff = off_all + NLAB;
    int* p1o  = off_all + NLAB + NDIS;
    int* p2o  = off_all + NLAB + NDIS + NPAT;
    int* lcur = cur_all;
    int* dcur = cur_all + NLAB;
    int* p1c  = cur_all + NLAB + NDIS;
    int* p2c  = cur_all + NLAB + NDIS + NPAT;

    cudaFuncSetAttribute(k_gemm, cudaFuncAttributeMaxDynamicSharedMemorySize, 65536);
    cudaFuncSetAttribute(k_mma, cudaFuncAttributeMaxDynamicSharedMemorySize, MMA_SMEM);
    cudaFuncSetAttribute(k_mma_fc1, cudaFuncAttributeMaxDynamicSharedMemorySize, MMA1_SMEM);

    static cudaStream_t sB = nullptr, sC = nullptr, sD = nullptr;
    static cudaEvent_t evRoot, evCSR, evE, evTD0, evTD1, evG0, evHP0, evBfin,
                       evW, evZ, evC2, evScan, evF2;
    if (!sB) {
        cudaStreamCreateWithFlags(&sB, cudaStreamNonBlocking);
        cudaStreamCreateWithFlags(&sC, cudaStreamNonBlocking);
        cudaStreamCreateWithFlags(&sD, cudaStreamNonBlocking);
        cudaEventCreateWithFlags(&evRoot, cudaEventDisableTiming);
        cudaEventCreateWithFlags(&evCSR,  cudaEventDisableTiming);
        cudaEventCreateWithFlags(&evE,    cudaEventDisableTiming);
        cudaEventCreateWithFlags(&evTD0,  cudaEventDisableTiming);
        cudaEventCreateWithFlags(&evTD1,  cudaEventDisableTiming);
        cudaEventCreateWithFlags(&evG0,   cudaEventDisableTiming);
        cudaEventCreateWithFlags(&evHP0,  cudaEventDisableTiming);
        cudaEventCreateWithFlags(&evBfin, cudaEventDisableTiming);
        cudaEventCreateWithFlags(&evW,    cudaEventDisableTiming);
        cudaEventCreateWithFlags(&evZ,    cudaEventDisableTiming);
        cudaEventCreateWithFlags(&evC2,   cudaEventDisableTiming);
        cudaEventCreateWithFlags(&evScan, cudaEventDisableTiming);
        cudaEventCreateWithFlags(&evF2,   cudaEventDisableTiming);
    }

    // fork
    cudaEventRecord(evRoot, 0);
    cudaStreamWaitEvent(sB, evRoot, 0);
    cudaStreamWaitEvent(sC, evRoot, 0);
    cudaStreamWaitEvent(sD, evRoot, 0);

    // ---- stream D: weight prep, then CSR half 2 ----
    k_cvt16<<<(8192 + 255) / 256, 256, 0, sD>>>(fc1W, fw16, 8192);
    k_addw16<<<(HH + 255) / 256, 256, 0, sD>>>(Wr[0] + 2 * HH, Wr[0] + 3 * HH, wt16a);
    k_addw16<<<(HH + 255) / 256, 256, 0, sD>>>(Wr[1] + 2 * HH, Wr[1] + 3 * HH, wt16b);
    cudaEventRecord(evW, sD);

    // ---- stream C: zero + CSR build (split with sD) ----
    k_zero4<<<(int)((Z_N4 + 255) / 256), 256, 0, sC>>>((float4*)(B + O_DA0), Z_N4);
    cudaEventRecord(evZ, sC);
    cudaStreamWaitEvent(sD, evZ, 0);
    k_count<<<1024, 256, 0, sD>>>(s2, d2, NE2, cp2, cd);
    cudaEventRecord(evC2, sD);
    k_count<<<4096, 256, 0, sC>>>(s1, d1, NE1, cp1, cl);
    cudaStreamWaitEvent(sC, evC2, 0);
    k_psum<<<SNB, 256, 0, sC>>>(cnt_all, part);
    k_scanpart<<<1, 256, 0, sC>>>(part, off_all + NTOTI);
    k_scanfinal<<<SNB, 256, 0, sC>>>(cnt_all, part, off_all, cur_all);
    cudaEventRecord(evScan, sC);
    cudaStreamWaitEvent(sD, evScan, 0);
    k_fill<<<1024, 256, 0, sD>>>(s2, d2, NE2, dcur, p2c, adj_all);
    cudaEventRecord(evF2, sD);
    k_fill<<<4096, 256, 0, sC>>>(s1, d1, NE1, lcur, p1c, adj_all);
    cudaStreamWaitEvent(sC, evF2, 0);
    cudaEventRecord(evCSR, sC);

    // ---- stream A (0): patient embedding (fp16 only) ----
    k_embed_pat<<<2048, 128>>>(x_pat, Wp, bp, hp16);
    cudaEventRecord(evE, 0);

    // ---- stream B: lab/dis embeddings + layer-0 lab/dis pipeline ----
    k_embed_lab<<<(int)((SZ_HL + 255) / 256), 256, 0, sB>>>(x_lab, Wlab, blab, hl[0]);
    k_embed_dis<<<(int)((SZ_HD + 255) / 256), 256, 0, sB>>>(x_dis, Wdis, bdis, hd[0]);
    k_gemm<<<444, 128, 65536, sB>>>(hl[0], Wl[0] + 2 * HH, nullptr, tl, tl16[0], NLAB, 0);
    k_gemm<<<63, 128, 65536, sB>>>(hd[0], Wl[0] + 3 * HH, nullptr, td, td16[0], NDIS, 0);
    cudaEventRecord(evTD0, sB);
    cudaStreamWaitEvent(sB, evE, 0);
    cudaStreamWaitEvent(sB, evCSR, 0);
    k_gather_mean<<<(NLAB * 32 + 255) / 256, 256, 0, sB>>>(loff, adj_all, hp16, la, NLAB);
    k_gather_mean_w8<<<(NDIS * 8 * 32 + 255) / 256, 256, 0, sB>>>(doff, adj_all, hp16, da[0], NDIS);
    cudaEventRecord(evG0, sB);
    k_gemm<<<444, 128, 65536, sB>>>(la, Wl[0], bl[0], hl[1], nullptr, NLAB, 0);
    k_gemm<<<444, 128, 65536, sB>>>(hl[0], Wr[0], nullptr, hl[1], nullptr, NLAB, GF_ACC);
    k_stats<<<1024, 128, 0, sB>>>(hl[1], NLAB, sm + 1 * H, sq + 1 * H);
    k_bn<<<2048, 256, 0, sB>>>(hl[1], nullptr, SZ_HL, 1.f / NLAB, sm + 1 * H, sq + 1 * H,
                               bng[0] + 1 * H, bnb[0] + 1 * H, 1);
    k_gemm<<<63, 128, 65536, sB>>>(da[0], Wl[0] + HH, bl[0] + H, hd[1], nullptr, NDIS, 0);
    k_gemm<<<63, 128, 65536, sB>>>(hd[0], Wr[0] + HH, nullptr, hd[1], nullptr, NDIS, GF_ACC);
    k_stats<<<500, 128, 0, sB>>>(hd[1], NDIS, sm + 2 * H, sq + 2 * H);
    k_bn<<<256, 256, 0, sB>>>(hd[1], nullptr, SZ_HD, 1.f / NDIS, sm + 2 * H, sq + 2 * H,
                              bng[0] + 2 * H, bnb[0] + 2 * H, 1);
    // layer-1 pre-transforms into the second buffers (no anti-dependency)
    k_gemm<<<444, 128, 65536, sB>>>(hl[1], Wl[1] + 2 * HH, nullptr, tl, tl16[1], NLAB, 0);
    k_gemm<<<63, 128, 65536, sB>>>(hd[1], Wl[1] + 3 * HH, nullptr, td, td16[1], NDIS, 0);
    cudaEventRecord(evTD1, sB);

    // ---- stream A: layer-0 patient pipeline ----
    cudaStreamWaitEvent(0, evW, 0);
    k_mma<<<444, 128, MMA_SMEM>>>(hp16, wt16a, hp[1], NPAT);
    cudaStreamWaitEvent(0, evCSR, 0);
    cudaStreamWaitEvent(0, evTD0, 0);
    k_gather_pat<<<NPAT / 8, 256>>>(p1o, adj_all, tl16[0], p2o, adj_all, td16[0],
                                    bl[0] + 2 * H, bl[0] + 3 * H, hp[1],
                                    sm + 0 * H, sq + 0 * H);
    cudaStreamWaitEvent(0, evG0, 0);   // hp16 v1 fully consumed before overwrite
    k_bn<<<8192, 256>>>(hp[1], hp16, SZ_HP, 1.f / NPAT, sm + 0 * H, sq + 0 * H,
                        bng[0] + 0 * H, bnb[0] + 0 * H, 0);
    cudaEventRecord(evHP0, 0);   // hp16 v2 ready

    // ---- stream B: layer-1 lab/dis pipeline ----
    cudaStreamWaitEvent(sB, evHP0, 0);
    k_gather_mean<<<(NLAB * 32 + 255) / 256, 256, 0, sB>>>(loff, adj_all, hp16, la, NLAB);
    k_gather_mean_w8<<<(NDIS * 8 * 32 + 255) / 256, 256, 0, sB>>>(doff, adj_all, hp16, da[1], NDIS);
    k_gemm<<<444, 128, 65536, sB>>>(la, Wl[1], bl[1], hl[0], nullptr, NLAB, 0);
    k_gemm<<<444, 128, 65536, sB>>>(hl[1], Wr[1], nullptr, hl[0], nullptr, NLAB, GF_ACC);
    k_stats<<<1024, 128, 0, sB>>>(hl[0], NLAB, sm + 4 * H, sq + 4 * H);
    k_bn<<<2048, 256, 0, sB>>>(hl[0], nullptr, SZ_HL, 1.f / NLAB, sm + 4 * H, sq + 4 * H,
                               bng[1] + 1 * H, bnb[1] + 1 * H, 1);
    k_gemm<<<63, 128, 65536, sB>>>(da[1], Wl[1] + HH, bl[1] + H, hd[0], nullptr, NDIS, 0);
    k_gemm<<<63, 128, 65536, sB>>>(hd[1], Wr[1] + HH, nullptr, hd[0], nullptr, NDIS, GF_ACC);
    k_stats<<<500, 128, 0, sB>>>(hd[0], NDIS, sm + 5 * H, sq + 5 * H);
    k_bn<<<256, 256, 0, sB>>>(hd[0], nullptr, SZ_HD, 1.f / NDIS, sm + 5 * H, sq + 5 * H,
                              bng[1] + 2 * H, bnb[1] + 2 * H, 1);
    cudaEventRecord(evBfin, sB);

    // ---- stream A: layer-1 patient pipeline + head ----
    k_mma<<<444, 128, MMA_SMEM>>>(hp16, wt16b, hp[0], NPAT);
    cudaStreamWaitEvent(0, evTD1, 0);
    k_gather_pat<<<NPAT / 8, 256>>>(p1o, adj_all, tl16[1], p2o, adj_all, td16[1],
                                    bl[1] + 2 * H, bl[1] + 3 * H, hp[0],
                                    sm + 3 * H, sq + 3 * H);
    k_bn<<<8192, 256>>>(hp[0], hp16b, SZ_HP, 1.f / NPAT, sm + 3 * H, sq + 3 * H,
                        bng[1] + 0 * H, bnb[1] + 0 * H, 0);
    k_mma_fc1<<<444, 128, MMA1_SMEM>>>(hp16b, fw16, fc1b, t1, NPAT);
    k_head<<<(NPAT + 3) / 4, 128>>>(t1, fc2W, fc2b, (float*)d_out);

    cudaStreamWaitEvent(0, evBfin, 0);
}